// round 1
// baseline (speedup 1.0000x reference)
#include <cuda_runtime.h>
#include <math.h>

// Problem constants
#define B_ 4
#define S_ 2048
#define C_ 512
#define H_ 8
#define D_ 64
#define NTOK (B_ * S_)          // 8192
#define ATT_SCALE 0.125f        // D^-0.5
#define LN_EPS 1e-5f

// ---------------------------------------------------------------------------
// Scratch buffers (static __device__ arrays: no allocation at runtime)
// ---------------------------------------------------------------------------
__device__ float g_q  [NTOK * C_];
__device__ float g_k  [NTOK * C_];
__device__ float g_v  [NTOK * C_];
__device__ float g_att[NTOK * C_];
__device__ float g_t0 [NTOK * C_];
__device__ float g_xln[NTOK * C_];
__device__ float g_t1 [NTOK * C_];

// ---------------------------------------------------------------------------
// SGEMM: C[M,N] = A[M,K] @ B[K,N] (+ bias). 128x128 tile, BK=8, 256 threads,
// 8x8 microtile per thread. M,N multiples of 128; K multiple of 8.
// ---------------------------------------------------------------------------
__global__ __launch_bounds__(256) void sgemm_k(
    const float* __restrict__ A, const float* __restrict__ Bw,
    const float* __restrict__ bias, float* __restrict__ Cmat,
    int M, int N, int K)
{
    __shared__ float As[8][128];
    __shared__ float Bs[8][128];

    const int tid = threadIdx.x;
    const int tx = tid & 15;       // 0..15 -> n
    const int ty = tid >> 4;       // 0..15 -> m
    const int m0 = blockIdx.y * 128;
    const int n0 = blockIdx.x * 128;

    const int a_row = tid >> 1;          // 0..127
    const int a_col = (tid & 1) << 2;    // 0 or 4
    const int b_row = tid >> 5;          // 0..7
    const int b_col = (tid & 31) << 2;   // 0..124

    float acc[8][8];
#pragma unroll
    for (int i = 0; i < 8; i++)
#pragma unroll
        for (int j = 0; j < 8; j++) acc[i][j] = 0.f;

    const float* Aptr = A + (size_t)(m0 + a_row) * K + a_col;
    const float* Bptr = Bw + (size_t)b_row * N + n0 + b_col;

    for (int k0 = 0; k0 < K; k0 += 8) {
        float4 av = *(const float4*)(Aptr + k0);
        As[a_col + 0][a_row] = av.x;
        As[a_col + 1][a_row] = av.y;
        As[a_col + 2][a_row] = av.z;
        As[a_col + 3][a_row] = av.w;
        float4 bv = *(const float4*)(Bptr + (size_t)k0 * N);
        *(float4*)&Bs[b_row][b_col] = bv;
        __syncthreads();

#pragma unroll
        for (int kk = 0; kk < 8; kk++) {
            float a[8], bb[8];
            *(float4*)&a[0]  = *(const float4*)&As[kk][ty * 8];
            *(float4*)&a[4]  = *(const float4*)&As[kk][ty * 8 + 4];
            *(float4*)&bb[0] = *(const float4*)&Bs[kk][tx * 8];
            *(float4*)&bb[4] = *(const float4*)&Bs[kk][tx * 8 + 4];
#pragma unroll
            for (int i = 0; i < 8; i++)
#pragma unroll
                for (int j = 0; j < 8; j++)
                    acc[i][j] += a[i] * bb[j];
        }
        __syncthreads();
    }

    float4 bsv0 = make_float4(0.f, 0.f, 0.f, 0.f);
    float4 bsv1 = make_float4(0.f, 0.f, 0.f, 0.f);
    if (bias) {
        bsv0 = *(const float4*)&bias[n0 + tx * 8];
        bsv1 = *(const float4*)&bias[n0 + tx * 8 + 4];
    }

#pragma unroll
    for (int i = 0; i < 8; i++) {
        float* crow = Cmat + (size_t)(m0 + ty * 8 + i) * N + n0 + tx * 8;
        float4 v0, v1;
        v0.x = acc[i][0] + bsv0.x; v0.y = acc[i][1] + bsv0.y;
        v0.z = acc[i][2] + bsv0.z; v0.w = acc[i][3] + bsv0.w;
        v1.x = acc[i][4] + bsv1.x; v1.y = acc[i][5] + bsv1.y;
        v1.z = acc[i][6] + bsv1.z; v1.w = acc[i][7] + bsv1.w;
        *(float4*)(crow)     = v0;
        *(float4*)(crow + 4) = v1;
    }
}

// ---------------------------------------------------------------------------
// LayerNorm over last dim C_=512: out = LN(in (+res)) * w + b
// One block per row, 128 threads, 4 elems per thread.
// ---------------------------------------------------------------------------
__global__ __launch_bounds__(128) void ln_k(
    const float* __restrict__ in, const float* __restrict__ res,
    const float* __restrict__ w, const float* __restrict__ b,
    float* __restrict__ out)
{
    const int row = blockIdx.x;
    const int t = threadIdx.x;

    float4 v = *(const float4*)(in + (size_t)row * C_ + t * 4);
    if (res) {
        float4 r = *(const float4*)(res + (size_t)row * C_ + t * 4);
        v.x += r.x; v.y += r.y; v.z += r.z; v.w += r.w;
    }
    float s  = v.x + v.y + v.z + v.w;
    float s2 = v.x * v.x + v.y * v.y + v.z * v.z + v.w * v.w;
#pragma unroll
    for (int o = 16; o; o >>= 1) {
        s  += __shfl_xor_sync(0xffffffffu, s,  o);
        s2 += __shfl_xor_sync(0xffffffffu, s2, o);
    }
    __shared__ float rs[4], rs2[4];
    const int wid = t >> 5;
    if ((t & 31) == 0) { rs[wid] = s; rs2[wid] = s2; }
    __syncthreads();
    float S  = rs[0]  + rs[1]  + rs[2]  + rs[3];
    float S2 = rs2[0] + rs2[1] + rs2[2] + rs2[3];
    const float mean = S * (1.f / C_);
    const float var  = S2 * (1.f / C_) - mean * mean;
    const float inv  = rsqrtf(var + LN_EPS);

    float4 wv = *(const float4*)(w + t * 4);
    float4 bv = *(const float4*)(b + t * 4);
    float4 o;
    o.x = (v.x - mean) * inv * wv.x + bv.x;
    o.y = (v.y - mean) * inv * wv.y + bv.y;
    o.z = (v.z - mean) * inv * wv.z + bv.z;
    o.w = (v.w - mean) * inv * wv.w + bv.w;
    *(float4*)(out + (size_t)row * C_ + t * 4) = o;
}

// ---------------------------------------------------------------------------
// Flash attention (fp32, causal). 64-row Q tile per block, 64-col K tiles,
// online softmax. Q/K/V layout: [NTOK, H*D], head h at cols h*64..h*64+63.
// grid = (S/64, B*H), 256 threads, dynamic smem.
// ---------------------------------------------------------------------------
#define FTS 65  // padded tile stride (floats)
#define FLASH_SMEM ((4 * 64 * FTS + 4 * 64 + 4 * 64) * 4)  // 68608 bytes

__global__ __launch_bounds__(256) void flash_k(
    const float* __restrict__ Qg, const float* __restrict__ Kg,
    const float* __restrict__ Vg, float* __restrict__ Og)
{
    extern __shared__ float sm[];
    float* Qs      = sm;                 // 64*FTS
    float* Ks      = Qs + 64 * FTS;
    float* Vs      = Ks + 64 * FTS;
    float* Ss      = Vs + 64 * FTS;
    float* m_sh    = Ss + 64 * FTS;      // 64
    float* l_sh    = m_sh + 64;          // 64
    float* corr_sh = l_sh + 64;          // 64
    float* mnew_sh = corr_sh + 64;       // 64
    float* part    = mnew_sh + 64;       // 4*64

    const int qt = blockIdx.x;
    const int bh = blockIdx.y;
    const int b  = bh >> 3;
    const int h  = bh & 7;
    const int tid = threadIdx.x;
    const int tx = tid & 15, ty = tid >> 4;
    const int row = tid & 63, seg = tid >> 6;

    const size_t base = (size_t)b * S_ * C_ + (size_t)h * D_;
    const int q0 = qt * 64;

    // Load Q tile
    for (int i = tid; i < 64 * 16; i += 256) {
        const int rr = i >> 4, cc = (i & 15) << 2;
        float4 v = *(const float4*)&Qg[base + (size_t)(q0 + rr) * C_ + cc];
        float* p = &Qs[rr * FTS + cc];
        p[0] = v.x; p[1] = v.y; p[2] = v.z; p[3] = v.w;
    }
    if (tid < 64) { m_sh[tid] = -1e30f; l_sh[tid] = 0.f; }

    float acc[4][4];
#pragma unroll
    for (int i = 0; i < 4; i++)
#pragma unroll
        for (int j = 0; j < 4; j++) acc[i][j] = 0.f;

    for (int kt = 0; kt <= qt; kt++) {
        const int k0 = kt * 64;
        __syncthreads();   // Q ready (first iter) / previous phase C done

        // Load K & V tiles
        for (int i = tid; i < 64 * 16; i += 256) {
            const int rr = i >> 4, cc = (i & 15) << 2;
            float4 kv = *(const float4*)&Kg[base + (size_t)(k0 + rr) * C_ + cc];
            float* p = &Ks[rr * FTS + cc];
            p[0] = kv.x; p[1] = kv.y; p[2] = kv.z; p[3] = kv.w;
            float4 vv = *(const float4*)&Vg[base + (size_t)(k0 + rr) * C_ + cc];
            float* q = &Vs[rr * FTS + cc];
            q[0] = vv.x; q[1] = vv.y; q[2] = vv.z; q[3] = vv.w;
        }
        __syncthreads();

        // Phase A: S = (Q @ K^T) * scale  (+ causal mask on diagonal tile)
        {
            float sacc[4][4];
#pragma unroll
            for (int i = 0; i < 4; i++)
#pragma unroll
                for (int j = 0; j < 4; j++) sacc[i][j] = 0.f;

            const float* qrow = Qs + ty * 4 * FTS;
            const float* krow = Ks + tx * 4 * FTS;
#pragma unroll 8
            for (int d = 0; d < 64; d++) {
                const float a0 = qrow[d];
                const float a1 = qrow[FTS + d];
                const float a2 = qrow[2 * FTS + d];
                const float a3 = qrow[3 * FTS + d];
                const float b0 = krow[d];
                const float b1 = krow[FTS + d];
                const float b2 = krow[2 * FTS + d];
                const float b3 = krow[3 * FTS + d];
                sacc[0][0] += a0 * b0; sacc[0][1] += a0 * b1; sacc[0][2] += a0 * b2; sacc[0][3] += a0 * b3;
                sacc[1][0] += a1 * b0; sacc[1][1] += a1 * b1; sacc[1][2] += a1 * b2; sacc[1][3] += a1 * b3;
                sacc[2][0] += a2 * b0; sacc[2][1] += a2 * b1; sacc[2][2] += a2 * b2; sacc[2][3] += a2 * b3;
                sacc[3][0] += a3 * b0; sacc[3][1] += a3 * b1; sacc[3][2] += a3 * b2; sacc[3][3] += a3 * b3;
            }
            const bool diag = (kt == qt);
#pragma unroll
            for (int i = 0; i < 4; i++) {
                const int r = ty * 4 + i;
#pragma unroll
                for (int j = 0; j < 4; j++) {
                    const int c = tx * 4 + j;
                    float val = sacc[i][j] * ATT_SCALE;
                    if (diag && c > r) val = -1e30f;
                    Ss[r * FTS + c] = val;
                }
            }
        }
        __syncthreads();

        // Phase B1: per-row partial max
        {
            float pm = -1e30f;
            const float* sr = &Ss[row * FTS + seg * 16];
#pragma unroll
            for (int j = 0; j < 16; j++) pm = fmaxf(pm, sr[j]);
            part[seg * 64 + row] = pm;
        }
        __syncthreads();
        if (tid < 64) {
            const float mx = fmaxf(fmaxf(part[tid], part[64 + tid]),
                                   fmaxf(part[128 + tid], part[192 + tid]));
            const float mo = m_sh[tid];
            const float mn = fmaxf(mo, mx);
            mnew_sh[tid] = mn;
            corr_sh[tid] = __expf(mo - mn);
            m_sh[tid] = mn;
        }
        __syncthreads();

        // Phase B2: exponentiate + per-row partial sum
        {
            const float mn = mnew_sh[row];
            float ps = 0.f;
            float* sr = &Ss[row * FTS + seg * 16];
#pragma unroll
            for (int j = 0; j < 16; j++) {
                const float p = __expf(sr[j] - mn);
                sr[j] = p;
                ps += p;
            }
            part[seg * 64 + row] = ps;
        }
        __syncthreads();
        if (tid < 64) {
            l_sh[tid] = l_sh[tid] * corr_sh[tid] +
                        (part[tid] + part[64 + tid] + part[128 + tid] + part[192 + tid]);
        }

        // Phase C: acc = acc*corr + P @ V
        {
            float cr0 = corr_sh[ty * 4 + 0];
            float cr1 = corr_sh[ty * 4 + 1];
            float cr2 = corr_sh[ty * 4 + 2];
            float cr3 = corr_sh[ty * 4 + 3];
#pragma unroll
            for (int j = 0; j < 4; j++) {
                acc[0][j] *= cr0; acc[1][j] *= cr1;
                acc[2][j] *= cr2; acc[3][j] *= cr3;
            }
            const float* srow = Ss + ty * 4 * FTS;
            const float* vcol = Vs + tx * 4;
#pragma unroll 8
            for (int kk = 0; kk < 64; kk++) {
                const float p0 = srow[kk];
                const float p1 = srow[FTS + kk];
                const float p2 = srow[2 * FTS + kk];
                const float p3 = srow[3 * FTS + kk];
                const float v0 = vcol[kk * FTS + 0];
                const float v1 = vcol[kk * FTS + 1];
                const float v2 = vcol[kk * FTS + 2];
                const float v3 = vcol[kk * FTS + 3];
                acc[0][0] += p0 * v0; acc[0][1] += p0 * v1; acc[0][2] += p0 * v2; acc[0][3] += p0 * v3;
                acc[1][0] += p1 * v0; acc[1][1] += p1 * v1; acc[1][2] += p1 * v2; acc[1][3] += p1 * v3;
                acc[2][0] += p2 * v0; acc[2][1] += p2 * v1; acc[2][2] += p2 * v2; acc[2][3] += p2 * v3;
                acc[3][0] += p3 * v0; acc[3][1] += p3 * v1; acc[3][2] += p3 * v2; acc[3][3] += p3 * v3;
            }
        }
    }
    __syncthreads();  // l_sh final values visible

    // Epilogue: normalize and store
#pragma unroll
    for (int i = 0; i < 4; i++) {
        const int r = ty * 4 + i;
        const float invl = 1.f / l_sh[r];
        float4 o;
        o.x = acc[i][0] * invl;
        o.y = acc[i][1] * invl;
        o.z = acc[i][2] * invl;
        o.w = acc[i][3] * invl;
        *(float4*)&Og[base + (size_t)(q0 + r) * C_ + tx * 4] = o;
    }
}

// ---------------------------------------------------------------------------
// Launcher
// ---------------------------------------------------------------------------
extern "C" void kernel_launch(void* const* d_in, const int* in_sizes, int n_in,
                              void* d_out, int out_size)
{
    (void)in_sizes; (void)n_in; (void)out_size;

    const float* x        = (const float*)d_in[0];
    const float* Wq       = (const float*)d_in[1];
    const float* Wk       = (const float*)d_in[2];
    const float* Wv       = (const float*)d_in[3];
    const float* Wo       = (const float*)d_in[4];
    const float* ln1_w    = (const float*)d_in[5];
    const float* ln1_b    = (const float*)d_in[6];
    const float* ff_ln1_w = (const float*)d_in[7];
    const float* ff_ln1_b = (const float*)d_in[8];
    const float* ff_w1    = (const float*)d_in[9];
    const float* ff_b1    = (const float*)d_in[10];
    const float* ff_ln2_w = (const float*)d_in[11];
    const float* ff_ln2_b = (const float*)d_in[12];
    const float* ff_w2    = (const float*)d_in[13];
    const float* ff_b2    = (const float*)d_in[14];
    const float* ln2_w    = (const float*)d_in[15];
    const float* ln2_b    = (const float*)d_in[16];
    float* out = (float*)d_out;

    float *q, *k, *v, *att, *t0, *xln, *t1;
    cudaGetSymbolAddress((void**)&q,   g_q);
    cudaGetSymbolAddress((void**)&k,   g_k);
    cudaGetSymbolAddress((void**)&v,   g_v);
    cudaGetSymbolAddress((void**)&att, g_att);
    cudaGetSymbolAddress((void**)&t0,  g_t0);
    cudaGetSymbolAddress((void**)&xln, g_xln);
    cudaGetSymbolAddress((void**)&t1,  g_t1);

    cudaFuncSetAttribute(flash_k, cudaFuncAttributeMaxDynamicSharedMemorySize,
                         FLASH_SMEM);

    const dim3 ggrid(C_ / 128, NTOK / 128);   // (4, 64)

    // QKV projections
    sgemm_k<<<ggrid, 256>>>(x, Wq, nullptr, q, NTOK, C_, C_);
    sgemm_k<<<ggrid, 256>>>(x, Wk, nullptr, k, NTOK, C_, C_);
    sgemm_k<<<ggrid, 256>>>(x, Wv, nullptr, v, NTOK, C_, C_);

    // Causal flash attention
    flash_k<<<dim3(S_ / 64, B_ * H_), 256, FLASH_SMEM>>>(q, k, v, att);

    // Output projection
    sgemm_k<<<ggrid, 256>>>(att, Wo, nullptr, t0, NTOK, C_, C_);

    // x_ln = LN(attn_out + x)
    ln_k<<<NTOK, 128>>>(t0, x, ln1_w, ln1_b, xln);

    // h = LN(x_ln) @ ff_w1 + b1
    ln_k<<<NTOK, 128>>>(xln, nullptr, ff_ln1_w, ff_ln1_b, t0);
    sgemm_k<<<ggrid, 256>>>(t0, ff_w1, ff_b1, t1, NTOK, C_, C_);

    // h = LN(h) @ ff_w2 + b2
    ln_k<<<NTOK, 128>>>(t1, nullptr, ff_ln2_w, ff_ln2_b, t0);
    sgemm_k<<<ggrid, 256>>>(t0, ff_w2, ff_b2, t1, NTOK, C_, C_);

    // out = LN(h + x_ln)
    ln_k<<<NTOK, 128>>>(t1, xln, ln2_w, ln2_b, out);
}

// round 3
// speedup vs baseline: 2.4065x; 2.4065x over previous
#include <cuda_runtime.h>
#include <cuda_bf16.h>
#include <math.h>
#include <stdint.h>

// Problem constants
#define B_ 4
#define S_ 2048
#define C_ 512
#define H_ 8
#define D_ 64
#define NTOK (B_ * S_)          // 8192
#define ATT_SCALE 0.125f
#define LN_EPS 1e-5f

// ---------------------------------------------------------------------------
// Scratch buffers
// ---------------------------------------------------------------------------
__device__ float g_q  [NTOK * C_];
__device__ float g_k  [NTOK * C_];
__device__ float g_v  [NTOK * C_];
__device__ float g_att[NTOK * C_];
__device__ float g_t0 [NTOK * C_];
__device__ float g_xln[NTOK * C_];
__device__ float g_t1 [NTOK * C_];

// ---------------------------------------------------------------------------
// Helpers: smem addr, ldmatrix, mma (all base-target instructions, sm_80+)
// ---------------------------------------------------------------------------
__device__ __forceinline__ uint32_t smem_u32(const void* p) {
    uint32_t a;
    asm("{ .reg .u64 t; cvta.to.shared.u64 t, %1; cvt.u32.u64 %0, t; }"
        : "=r"(a) : "l"(p));
    return a;
}

__device__ __forceinline__ void ldsm4(uint32_t* r, uint32_t addr) {
    asm volatile("ldmatrix.sync.aligned.m8n8.x4.shared.b16 {%0,%1,%2,%3}, [%4];"
                 : "=r"(r[0]), "=r"(r[1]), "=r"(r[2]), "=r"(r[3]) : "r"(addr));
}
__device__ __forceinline__ void ldsm4t(uint32_t* r, uint32_t addr) {
    asm volatile("ldmatrix.sync.aligned.m8n8.x4.trans.shared.b16 {%0,%1,%2,%3}, [%4];"
                 : "=r"(r[0]), "=r"(r[1]), "=r"(r[2]), "=r"(r[3]) : "r"(addr));
}

// D = A(16x16 bf16) * B(16x8 bf16) + D, fp32 accum
__device__ __forceinline__ void mma16816(float* c, const uint32_t* a, const uint32_t* b) {
    asm volatile(
        "mma.sync.aligned.m16n8k16.row.col.f32.bf16.bf16.f32 "
        "{%0,%1,%2,%3},{%4,%5,%6,%7},{%8,%9},{%0,%1,%2,%3};"
        : "+f"(c[0]), "+f"(c[1]), "+f"(c[2]), "+f"(c[3])
        : "r"(a[0]), "r"(a[1]), "r"(a[2]), "r"(a[3]), "r"(b[0]), "r"(b[1]));
}

__device__ __forceinline__ uint16_t f2bf(float x) {
    __nv_bfloat16 b = __float2bfloat16(x);
    return *(uint16_t*)&b;
}
__device__ __forceinline__ float bf2f(uint16_t u) {
    __nv_bfloat16 b = *(__nv_bfloat16*)&u;
    return __bfloat162float(b);
}
// Split a pair of fp32 into packed bf16 hi / lo words
__device__ __forceinline__ void split2(float x0, float x1, uint32_t& hi, uint32_t& lo) {
    uint16_t h0 = f2bf(x0), h1 = f2bf(x1);
    uint16_t l0 = f2bf(x0 - bf2f(h0)), l1 = f2bf(x1 - bf2f(h1));
    hi = (uint32_t)h0 | ((uint32_t)h1 << 16);
    lo = (uint32_t)l0 | ((uint32_t)l1 << 16);
}

// ---------------------------------------------------------------------------
// bf16x3 GEMM via mma.sync. C[M,512] = A[M,512] @ W[512,512] (+bias)
// Tile 128x128, BK=32, 256 threads (8 warps; warp = 64x32).
// grid = (4, M/128, nz); z selects weight/out for fused QKV.
// ---------------------------------------------------------------------------
#define GSA 40    // A smem row stride (bf16 elems)
#define GSB 136   // B smem row stride
#define GOFF_AHI 0
#define GOFF_ALO 10240
#define GOFF_BHI 20480
#define GOFF_BLO 29184
#define GEMM_SMEM 37888

__global__ __launch_bounds__(256) void gemm_tc(
    const float* __restrict__ A,
    const float* __restrict__ B0, const float* __restrict__ B1,
    const float* __restrict__ B2,
    float* __restrict__ C0, float* __restrict__ C1, float* __restrict__ C2,
    const float* __restrict__ bias)
{
    extern __shared__ char sm[];
    const uint32_t smb = smem_u32(sm);
    const int tid = threadIdx.x;
    const int wid = tid >> 5, lane = tid & 31;
    const int g = lane >> 2, tig = lane & 3;
    const int wm = wid >> 2, wn = wid & 3;

    const float* Bw = (blockIdx.z == 0) ? B0 : (blockIdx.z == 1) ? B1 : B2;
    float* Cm       = (blockIdx.z == 0) ? C0 : (blockIdx.z == 1) ? C1 : C2;

    const int n0 = blockIdx.x * 128;
    const int m0 = blockIdx.y * 128;

    float c[4][4][4];
#pragma unroll
    for (int i = 0; i < 4; i++)
#pragma unroll
        for (int j = 0; j < 4; j++)
#pragma unroll
            for (int e = 0; e < 4; e++) c[i][j][e] = 0.f;

    const int ar = tid >> 1, ak = (tid & 1) * 16;
    const int br = tid >> 3, bn = (tid & 7) * 16;
    const float* Ag = A + (size_t)(m0 + ar) * 512 + ak;
    const float* Bg = Bw + (size_t)br * 512 + n0 + bn;

    for (int k0 = 0; k0 < 512; k0 += 32) {
        float4 av[4], bv[4];
#pragma unroll
        for (int j = 0; j < 4; j++) {
            av[j] = *(const float4*)(Ag + k0 + 4 * j);
            bv[j] = *(const float4*)(Bg + (size_t)k0 * 512 + 4 * j);
        }
        __syncthreads();
#pragma unroll
        for (int j = 0; j < 4; j++) {
            uint32_t h0, l0, h1, l1;
            split2(av[j].x, av[j].y, h0, l0);
            split2(av[j].z, av[j].w, h1, l1);
            const uint32_t off = (uint32_t)(ar * GSA + ak + 4 * j) * 2;
            *(uint2*)(sm + GOFF_AHI + off) = make_uint2(h0, h1);
            *(uint2*)(sm + GOFF_ALO + off) = make_uint2(l0, l1);
            split2(bv[j].x, bv[j].y, h0, l0);
            split2(bv[j].z, bv[j].w, h1, l1);
            const uint32_t bof = (uint32_t)(br * GSB + bn + 4 * j) * 2;
            *(uint2*)(sm + GOFF_BHI + bof) = make_uint2(h0, h1);
            *(uint2*)(sm + GOFF_BLO + bof) = make_uint2(l0, l1);
        }
        __syncthreads();

#pragma unroll
        for (int kk = 0; kk < 32; kk += 16) {
            uint32_t ah[4][4], al[4][4];
#pragma unroll
            for (int mf = 0; mf < 4; mf++) {
                const uint32_t ae =
                    (uint32_t)((wm * 64 + mf * 16 + (lane & 15)) * GSA +
                               kk + ((lane >> 4) << 3)) * 2;
                ldsm4(ah[mf], smb + GOFF_AHI + ae);
                ldsm4(al[mf], smb + GOFF_ALO + ae);
            }
            uint32_t bh[4][2], bl[4][2];
#pragma unroll
            for (int nfp = 0; nfp < 2; nfp++) {
                const uint32_t be =
                    (uint32_t)((kk + (lane & 7) + (((lane >> 3) & 1) << 3)) * GSB +
                               wn * 32 + nfp * 16 + ((lane >> 4) << 3)) * 2;
                uint32_t r[4];
                ldsm4t(r, smb + GOFF_BHI + be);
                bh[nfp * 2][0] = r[0]; bh[nfp * 2][1] = r[1];
                bh[nfp * 2 + 1][0] = r[2]; bh[nfp * 2 + 1][1] = r[3];
                ldsm4t(r, smb + GOFF_BLO + be);
                bl[nfp * 2][0] = r[0]; bl[nfp * 2][1] = r[1];
                bl[nfp * 2 + 1][0] = r[2]; bl[nfp * 2 + 1][1] = r[3];
            }
#pragma unroll
            for (int mf = 0; mf < 4; mf++)
#pragma unroll
                for (int nf = 0; nf < 4; nf++) {
                    mma16816(c[mf][nf], ah[mf], bh[nf]);
                    mma16816(c[mf][nf], ah[mf], bl[nf]);
                    mma16816(c[mf][nf], al[mf], bh[nf]);
                }
        }
    }

    // Epilogue
#pragma unroll
    for (int mf = 0; mf < 4; mf++) {
        const int row0 = m0 + wm * 64 + mf * 16 + g;
        const int row1 = row0 + 8;
#pragma unroll
        for (int nf = 0; nf < 4; nf++) {
            const int col = n0 + wn * 32 + nf * 8 + tig * 2;
            float bx = 0.f, by = 0.f;
            if (bias) { bx = bias[col]; by = bias[col + 1]; }
            float2 o0 = make_float2(c[mf][nf][0] + bx, c[mf][nf][1] + by);
            float2 o1 = make_float2(c[mf][nf][2] + bx, c[mf][nf][3] + by);
            *(float2*)(Cm + (size_t)row0 * 512 + col) = o0;
            *(float2*)(Cm + (size_t)row1 * 512 + col) = o1;
        }
    }
}

// ---------------------------------------------------------------------------
// LayerNorm over last dim 512
// ---------------------------------------------------------------------------
__global__ __launch_bounds__(128) void ln_k(
    const float* __restrict__ in, const float* __restrict__ res,
    const float* __restrict__ w, const float* __restrict__ b,
    float* __restrict__ out)
{
    const int row = blockIdx.x;
    const int t = threadIdx.x;

    float4 v = *(const float4*)(in + (size_t)row * C_ + t * 4);
    if (res) {
        float4 r = *(const float4*)(res + (size_t)row * C_ + t * 4);
        v.x += r.x; v.y += r.y; v.z += r.z; v.w += r.w;
    }
    float s  = v.x + v.y + v.z + v.w;
    float s2 = v.x * v.x + v.y * v.y + v.z * v.z + v.w * v.w;
#pragma unroll
    for (int o = 16; o; o >>= 1) {
        s  += __shfl_xor_sync(0xffffffffu, s,  o);
        s2 += __shfl_xor_sync(0xffffffffu, s2, o);
    }
    __shared__ float rs[4], rs2[4];
    const int wid = t >> 5;
    if ((t & 31) == 0) { rs[wid] = s; rs2[wid] = s2; }
    __syncthreads();
    float S  = rs[0]  + rs[1]  + rs[2]  + rs[3];
    float S2 = rs2[0] + rs2[1] + rs2[2] + rs2[3];
    const float mean = S * (1.f / C_);
    const float var  = S2 * (1.f / C_) - mean * mean;
    const float inv  = rsqrtf(var + LN_EPS);

    float4 wv = *(const float4*)(w + t * 4);
    float4 bv = *(const float4*)(b + t * 4);
    float4 o;
    o.x = (v.x - mean) * inv * wv.x + bv.x;
    o.y = (v.y - mean) * inv * wv.y + bv.y;
    o.z = (v.z - mean) * inv * wv.z + bv.z;
    o.w = (v.w - mean) * inv * wv.w + bv.w;
    *(float4*)(out + (size_t)row * C_ + t * 4) = o;
}

// ---------------------------------------------------------------------------
// Flash attention, bf16x3 mma.sync, causal. 64 q-rows per block.
// 256 threads = 8 warps; warp (mw=wid>>1, nw=wid&1) covers rows 16*mw,
// cols 32*nw (both for scores [q][kpos] and output [q][d]).
// ---------------------------------------------------------------------------
#define FS 72  // smem row stride (bf16 elems)
#define FOFF_QHI 0
#define FOFF_QLO 9216
#define FOFF_KHI 18432
#define FOFF_KLO 27648
#define FOFF_VHI 36864
#define FOFF_VLO 46080
#define FOFF_PHI 55296
#define FOFF_PLO 64512
#define FOFF_ST  73728
#define FLASH_SMEM 75264
// state float layout at FOFF_ST: [0..63]=m, [64..127]=l, [128..191]=corr,
// [192..255]=mnew, [256..383]=partials

__global__ __launch_bounds__(256) void flash_k(
    const float* __restrict__ Qg, const float* __restrict__ Kg,
    const float* __restrict__ Vg, float* __restrict__ Og)
{
    extern __shared__ char sm[];
    const uint32_t smb = smem_u32(sm);
    float* stf = (float*)(sm + FOFF_ST);

    const int tid = threadIdx.x;
    const int wid = tid >> 5, lane = tid & 31;
    const int g = lane >> 2, tig = lane & 3;
    const int mw = wid >> 1, nw = wid & 1;

    const int qt = blockIdx.x;
    const int bh = blockIdx.y;
    const int b  = bh >> 3, h = bh & 7;
    const size_t base = (size_t)b * S_ * C_ + (size_t)h * D_;
    const int q0 = qt * 64;

    // Load + split Q tile [64][64]
    const int lr = tid >> 2, ld = (tid & 3) * 16;
    {
        const float* qp = Qg + base + (size_t)(q0 + lr) * C_ + ld;
#pragma unroll
        for (int j = 0; j < 4; j++) {
            float4 v = *(const float4*)(qp + 4 * j);
            uint32_t h0, l0, h1, l1;
            split2(v.x, v.y, h0, l0);
            split2(v.z, v.w, h1, l1);
            const uint32_t off = (uint32_t)(lr * FS + ld + 4 * j) * 2;
            *(uint2*)(sm + FOFF_QHI + off) = make_uint2(h0, h1);
            *(uint2*)(sm + FOFF_QLO + off) = make_uint2(l0, l1);
        }
    }
    if (tid < 64) { stf[tid] = -1e30f; stf[64 + tid] = 0.f; }

    float acc[4][4];
#pragma unroll
    for (int i = 0; i < 4; i++)
#pragma unroll
        for (int j = 0; j < 4; j++) acc[i][j] = 0.f;

    const int rl0 = mw * 16 + g, rl1 = rl0 + 8;

    for (int kt = 0; kt <= qt; kt++) {
        __syncthreads();
        const int k0g = kt * 64;
        {
            const float* kp = Kg + base + (size_t)(k0g + lr) * C_ + ld;
            const float* vp = Vg + base + (size_t)(k0g + lr) * C_ + ld;
#pragma unroll
            for (int j = 0; j < 4; j++) {
                float4 kv = *(const float4*)(kp + 4 * j);
                float4 vv = *(const float4*)(vp + 4 * j);
                uint32_t h0, l0, h1, l1;
                const uint32_t off = (uint32_t)(lr * FS + ld + 4 * j) * 2;
                split2(kv.x, kv.y, h0, l0);
                split2(kv.z, kv.w, h1, l1);
                *(uint2*)(sm + FOFF_KHI + off) = make_uint2(h0, h1);
                *(uint2*)(sm + FOFF_KLO + off) = make_uint2(l0, l1);
                split2(vv.x, vv.y, h0, l0);
                split2(vv.z, vv.w, h1, l1);
                *(uint2*)(sm + FOFF_VHI + off) = make_uint2(h0, h1);
                *(uint2*)(sm + FOFF_VLO + off) = make_uint2(l0, l1);
            }
        }
        __syncthreads();

        // ---- scores S = Q @ K^T (bf16x3) ----
        float s[4][4];
#pragma unroll
        for (int i = 0; i < 4; i++)
#pragma unroll
            for (int j = 0; j < 4; j++) s[i][j] = 0.f;

#pragma unroll
        for (int kf = 0; kf < 4; kf++) {
            const uint32_t ae =
                (uint32_t)((mw * 16 + (lane & 15)) * FS + kf * 16 +
                           ((lane >> 4) << 3)) * 2;
            uint32_t aqh[4], aql[4];
            ldsm4(aqh, smb + FOFF_QHI + ae);
            ldsm4(aql, smb + FOFF_QLO + ae);
            uint32_t bkh[4][2], bkl[4][2];
#pragma unroll
            for (int nfp = 0; nfp < 2; nfp++) {
                const uint32_t be =
                    (uint32_t)((nw * 32 + nfp * 16 + (lane & 7) +
                                ((lane >> 4) << 3)) * FS +
                               kf * 16 + (((lane >> 3) & 1) << 3)) * 2;
                uint32_t r[4];
                ldsm4(r, smb + FOFF_KHI + be);
                bkh[nfp * 2][0] = r[0]; bkh[nfp * 2][1] = r[1];
                bkh[nfp * 2 + 1][0] = r[2]; bkh[nfp * 2 + 1][1] = r[3];
                ldsm4(r, smb + FOFF_KLO + be);
                bkl[nfp * 2][0] = r[0]; bkl[nfp * 2][1] = r[1];
                bkl[nfp * 2 + 1][0] = r[2]; bkl[nfp * 2 + 1][1] = r[3];
            }
#pragma unroll
            for (int nf = 0; nf < 4; nf++) {
                mma16816(s[nf], aqh, bkh[nf]);
                mma16816(s[nf], aqh, bkl[nf]);
                mma16816(s[nf], aql, bkh[nf]);
            }
        }

        // scale + causal mask
        const bool diag = (kt == qt);
#pragma unroll
        for (int nf = 0; nf < 4; nf++) {
#pragma unroll
            for (int e = 0; e < 4; e++) s[nf][e] *= ATT_SCALE;
            if (diag) {
                const int cc = nw * 32 + nf * 8 + tig * 2;
                if (cc     > rl0) s[nf][0] = -1e30f;
                if (cc + 1 > rl0) s[nf][1] = -1e30f;
                if (cc     > rl1) s[nf][2] = -1e30f;
                if (cc + 1 > rl1) s[nf][3] = -1e30f;
            }
        }

        // row max (warp part)
        float r0m = -1e30f, r1m = -1e30f;
#pragma unroll
        for (int nf = 0; nf < 4; nf++) {
            r0m = fmaxf(r0m, fmaxf(s[nf][0], s[nf][1]));
            r1m = fmaxf(r1m, fmaxf(s[nf][2], s[nf][3]));
        }
        r0m = fmaxf(r0m, __shfl_xor_sync(0xffffffffu, r0m, 1));
        r0m = fmaxf(r0m, __shfl_xor_sync(0xffffffffu, r0m, 2));
        r1m = fmaxf(r1m, __shfl_xor_sync(0xffffffffu, r1m, 1));
        r1m = fmaxf(r1m, __shfl_xor_sync(0xffffffffu, r1m, 2));
        if (tig == 0) {
            stf[256 + nw * 64 + rl0] = r0m;
            stf[256 + nw * 64 + rl1] = r1m;
        }
        __syncthreads();
        if (tid < 64) {
            const float mo = stf[tid];
            const float mx = fmaxf(stf[256 + tid], stf[320 + tid]);
            const float mn = fmaxf(mo, mx);
            stf[192 + tid] = mn;
            stf[128 + tid] = __expf(mo - mn);
            stf[tid] = mn;
        }
        __syncthreads();

        // exp, accumulate partial sums, store bf16-split P, rescale acc
        const float mn0 = stf[192 + rl0], mn1 = stf[192 + rl1];
        const float cr0 = stf[128 + rl0], cr1 = stf[128 + rl1];
        float rs0 = 0.f, rs1 = 0.f;
#pragma unroll
        for (int nf = 0; nf < 4; nf++) {
            acc[nf][0] *= cr0; acc[nf][1] *= cr0;
            acc[nf][2] *= cr1; acc[nf][3] *= cr1;
            const float p00 = __expf(s[nf][0] - mn0);
            const float p01 = __expf(s[nf][1] - mn0);
            const float p10 = __expf(s[nf][2] - mn1);
            const float p11 = __expf(s[nf][3] - mn1);
            rs0 += p00 + p01; rs1 += p10 + p11;
            const int cb = nw * 32 + nf * 8 + tig * 2;
            uint32_t hi, lo;
            split2(p00, p01, hi, lo);
            *(uint32_t*)(sm + FOFF_PHI + (uint32_t)(rl0 * FS + cb) * 2) = hi;
            *(uint32_t*)(sm + FOFF_PLO + (uint32_t)(rl0 * FS + cb) * 2) = lo;
            split2(p10, p11, hi, lo);
            *(uint32_t*)(sm + FOFF_PHI + (uint32_t)(rl1 * FS + cb) * 2) = hi;
            *(uint32_t*)(sm + FOFF_PLO + (uint32_t)(rl1 * FS + cb) * 2) = lo;
        }
        rs0 += __shfl_xor_sync(0xffffffffu, rs0, 1);
        rs0 += __shfl_xor_sync(0xffffffffu, rs0, 2);
        rs1 += __shfl_xor_sync(0xffffffffu, rs1, 1);
        rs1 += __shfl_xor_sync(0xffffffffu, rs1, 2);
        if (tig == 0) {
            stf[256 + nw * 64 + rl0] = rs0;
            stf[256 + nw * 64 + rl1] = rs1;
        }
        __syncthreads();
        if (tid < 64) {
            stf[64 + tid] = stf[64 + tid] * stf[128 + tid] +
                            stf[256 + tid] + stf[320 + tid];
        }

        // ---- PV: acc += P @ V (bf16x3) ----
#pragma unroll
        for (int kf = 0; kf < 4; kf++) {
            const uint32_t ae =
                (uint32_t)((mw * 16 + (lane & 15)) * FS + kf * 16 +
                           ((lane >> 4) << 3)) * 2;
            uint32_t aph[4], apl[4];
            ldsm4(aph, smb + FOFF_PHI + ae);
            ldsm4(apl, smb + FOFF_PLO + ae);
            uint32_t bvh[4][2], bvl[4][2];
#pragma unroll
            for (int nfp = 0; nfp < 2; nfp++) {
                const uint32_t be =
                    (uint32_t)((kf * 16 + (lane & 7) + (((lane >> 3) & 1) << 3)) * FS +
                               nw * 32 + nfp * 16 + ((lane >> 4) << 3)) * 2;
                uint32_t r[4];
                ldsm4t(r, smb + FOFF_VHI + be);
                bvh[nfp * 2][0] = r[0]; bvh[nfp * 2][1] = r[1];
                bvh[nfp * 2 + 1][0] = r[2]; bvh[nfp * 2 + 1][1] = r[3];
                ldsm4t(r, smb + FOFF_VLO + be);
                bvl[nfp * 2][0] = r[0]; bvl[nfp * 2][1] = r[1];
                bvl[nfp * 2 + 1][0] = r[2]; bvl[nfp * 2 + 1][1] = r[3];
            }
#pragma unroll
            for (int nf = 0; nf < 4; nf++) {
                mma16816(acc[nf], aph, bvh[nf]);
                mma16816(acc[nf], aph, bvl[nf]);
                mma16816(acc[nf], apl, bvh[nf]);
            }
        }
    }
    __syncthreads();

    const float il0 = 1.f / stf[64 + rl0];
    const float il1 = 1.f / stf[64 + rl1];
#pragma unroll
    for (int nf = 0; nf < 4; nf++) {
        const int col = nw * 32 + nf * 8 + tig * 2;
        float2 o0 = make_float2(acc[nf][0] * il0, acc[nf][1] * il0);
        float2 o1 = make_float2(acc[nf][2] * il1, acc[nf][3] * il1);
        *(float2*)&Og[base + (size_t)(q0 + rl0) * C_ + col] = o0;
        *(float2*)&Og[base + (size_t)(q0 + rl1) * C_ + col] = o1;
    }
}

// ---------------------------------------------------------------------------
// Launcher
// ---------------------------------------------------------------------------
extern "C" void kernel_launch(void* const* d_in, const int* in_sizes, int n_in,
                              void* d_out, int out_size)
{
    (void)in_sizes; (void)n_in; (void)out_size;

    const float* x        = (const float*)d_in[0];
    const float* Wq       = (const float*)d_in[1];
    const float* Wk       = (const float*)d_in[2];
    const float* Wv       = (const float*)d_in[3];
    const float* Wo       = (const float*)d_in[4];
    const float* ln1_w    = (const float*)d_in[5];
    const float* ln1_b    = (const float*)d_in[6];
    const float* ff_ln1_w = (const float*)d_in[7];
    const float* ff_ln1_b = (const float*)d_in[8];
    const float* ff_w1    = (const float*)d_in[9];
    const float* ff_b1    = (const float*)d_in[10];
    const float* ff_ln2_w = (const float*)d_in[11];
    const float* ff_ln2_b = (const float*)d_in[12];
    const float* ff_w2    = (const float*)d_in[13];
    const float* ff_b2    = (const float*)d_in[14];
    const float* ln2_w    = (const float*)d_in[15];
    const float* ln2_b    = (const float*)d_in[16];
    float* out = (float*)d_out;

    float *q, *k, *v, *att, *t0, *xln, *t1;
    cudaGetSymbolAddress((void**)&q,   g_q);
    cudaGetSymbolAddress((void**)&k,   g_k);
    cudaGetSymbolAddress((void**)&v,   g_v);
    cudaGetSymbolAddress((void**)&att, g_att);
    cudaGetSymbolAddress((void**)&t0,  g_t0);
    cudaGetSymbolAddress((void**)&xln, g_xln);
    cudaGetSymbolAddress((void**)&t1,  g_t1);

    cudaFuncSetAttribute(flash_k, cudaFuncAttributeMaxDynamicSharedMemorySize,
                         FLASH_SMEM);
    cudaFuncSetAttribute(gemm_tc, cudaFuncAttributeMaxDynamicSharedMemorySize,
                         GEMM_SMEM);

    const dim3 g3(C_ / 128, NTOK / 128, 3);
    const dim3 g1(C_ / 128, NTOK / 128, 1);

    // QKV projections (fused, z selects weight/out)
    gemm_tc<<<g3, 256, GEMM_SMEM>>>(x, Wq, Wk, Wv, q, k, v, nullptr);

    // Causal flash attention
    flash_k<<<dim3(S_ / 64, B_ * H_), 256, FLASH_SMEM>>>(q, k, v, att);

    // Output projection
    gemm_tc<<<g1, 256, GEMM_SMEM>>>(att, Wo, Wo, Wo, t0, t0, t0, nullptr);

    // x_ln = LN(attn_out + x)
    ln_k<<<NTOK, 128>>>(t0, x, ln1_w, ln1_b, xln);

    // h = LN(x_ln) @ ff_w1 + b1
    ln_k<<<NTOK, 128>>>(xln, nullptr, ff_ln1_w, ff_ln1_b, t0);
    gemm_tc<<<g1, 256, GEMM_SMEM>>>(t0, ff_w1, ff_w1, ff_w1, t1, t1, t1, ff_b1);

    // h = LN(h) @ ff_w2 + b2
    ln_k<<<NTOK, 128>>>(t1, nullptr, ff_ln2_w, ff_ln2_b, t0);
    gemm_tc<<<g1, 256, GEMM_SMEM>>>(t0, ff_w2, ff_w2, ff_w2, t1, t1, t1, ff_b2);

    // out = LN(h + x_ln)
    ln_k<<<NTOK, 128>>>(t1, xln, ln2_w, ln2_b, out);
}

// round 4
// speedup vs baseline: 2.8610x; 1.1889x over previous
#include <cuda_runtime.h>
#include <cuda_bf16.h>
#include <math.h>
#include <stdint.h>

#define B_ 4
#define S_ 2048
#define C_ 512
#define H_ 8
#define D_ 64
#define NTOK (B_ * S_)
#define ATT_SCALE 0.125f
#define LN_EPS 1e-5f
#define NC ((size_t)NTOK * C_)
#define CC ((size_t)C_ * C_)

// ---------------------------------------------------------------------------
// Scratch buffers
// ---------------------------------------------------------------------------
__device__ float g_t0 [NC];
__device__ float g_xln[NC];
__device__ float g_t1 [NC];

__device__ uint16_t g_xhi [NC],     g_xlo [NC];      // split x
__device__ uint16_t g_whi [6 * CC], g_wlo [6 * CC];  // split weights
__device__ uint16_t g_qkvhi[3 * NC], g_qkvlo[3 * NC];// split q,k,v
__device__ uint16_t g_atthi[NC],    g_attlo[NC];     // split attention out
__device__ uint16_t g_t0hi[NC],     g_t0lo[NC];      // split ln out (ff inputs)

// ---------------------------------------------------------------------------
// Helpers
// ---------------------------------------------------------------------------
__device__ __forceinline__ uint32_t smem_u32(const void* p) {
    uint32_t a;
    asm("{ .reg .u64 t; cvta.to.shared.u64 t, %1; cvt.u32.u64 %0, t; }"
        : "=r"(a) : "l"(p));
    return a;
}
__device__ __forceinline__ void ldsm4(uint32_t* r, uint32_t addr) {
    asm volatile("ldmatrix.sync.aligned.m8n8.x4.shared.b16 {%0,%1,%2,%3}, [%4];"
                 : "=r"(r[0]), "=r"(r[1]), "=r"(r[2]), "=r"(r[3]) : "r"(addr));
}
__device__ __forceinline__ void ldsm4t(uint32_t* r, uint32_t addr) {
    asm volatile("ldmatrix.sync.aligned.m8n8.x4.trans.shared.b16 {%0,%1,%2,%3}, [%4];"
                 : "=r"(r[0]), "=r"(r[1]), "=r"(r[2]), "=r"(r[3]) : "r"(addr));
}
__device__ __forceinline__ void mma16816(float* c, const uint32_t* a, const uint32_t* b) {
    asm volatile(
        "mma.sync.aligned.m16n8k16.row.col.f32.bf16.bf16.f32 "
        "{%0,%1,%2,%3},{%4,%5,%6,%7},{%8,%9},{%0,%1,%2,%3};"
        : "+f"(c[0]), "+f"(c[1]), "+f"(c[2]), "+f"(c[3])
        : "r"(a[0]), "r"(a[1]), "r"(a[2]), "r"(a[3]), "r"(b[0]), "r"(b[1]));
}
__device__ __forceinline__ void cpa16(uint32_t dst, const void* src) {
    asm volatile("cp.async.cg.shared.global [%0], [%1], 16;" :: "r"(dst), "l"(src));
}
#define CPA_COMMIT() asm volatile("cp.async.commit_group;")
#define CPA_WAIT0()  asm volatile("cp.async.wait_group 0;")
#define CPA_WAIT1()  asm volatile("cp.async.wait_group 1;")

__device__ __forceinline__ uint16_t f2bf(float x) {
    __nv_bfloat16 b = __float2bfloat16(x);
    return *(uint16_t*)&b;
}
__device__ __forceinline__ float bf2f(uint16_t u) {
    __nv_bfloat16 b = *(__nv_bfloat16*)&u;
    return __bfloat162float(b);
}
__device__ __forceinline__ void split2(float x0, float x1, uint32_t& hi, uint32_t& lo) {
    uint16_t h0 = f2bf(x0), h1 = f2bf(x1);
    uint16_t l0 = f2bf(x0 - bf2f(h0)), l1 = f2bf(x1 - bf2f(h1));
    hi = (uint32_t)h0 | ((uint32_t)h1 << 16);
    lo = (uint32_t)l0 | ((uint32_t)l1 << 16);
}

// ---------------------------------------------------------------------------
// Split kernels: fp32 -> bf16 hi/lo planes. 8 floats per thread.
// ---------------------------------------------------------------------------
__global__ __launch_bounds__(256) void split1_k(
    const float* __restrict__ in, uint16_t* __restrict__ hi,
    uint16_t* __restrict__ lo)
{
    const size_t i = ((size_t)blockIdx.x * 256 + threadIdx.x) * 8;
    float4 a = *(const float4*)(in + i);
    float4 b = *(const float4*)(in + i + 4);
    uint32_t h0, l0, h1, l1, h2, l2, h3, l3;
    split2(a.x, a.y, h0, l0); split2(a.z, a.w, h1, l1);
    split2(b.x, b.y, h2, l2); split2(b.z, b.w, h3, l3);
    *(uint4*)(hi + i) = make_uint4(h0, h1, h2, h3);
    *(uint4*)(lo + i) = make_uint4(l0, l1, l2, l3);
}

__global__ __launch_bounds__(256) void splitw_k(
    const float* __restrict__ w0, const float* __restrict__ w1,
    const float* __restrict__ w2, const float* __restrict__ w3,
    const float* __restrict__ w4, const float* __restrict__ w5,
    uint16_t* __restrict__ hi, uint16_t* __restrict__ lo)
{
    const int z = blockIdx.z;
    const float* w = (z == 0) ? w0 : (z == 1) ? w1 : (z == 2) ? w2 :
                     (z == 3) ? w3 : (z == 4) ? w4 : w5;
    const size_t j = ((size_t)blockIdx.x * 256 + threadIdx.x) * 8;
    const size_t o = (size_t)z * CC + j;
    float4 a = *(const float4*)(w + j);
    float4 b = *(const float4*)(w + j + 4);
    uint32_t h0, l0, h1, l1, h2, l2, h3, l3;
    split2(a.x, a.y, h0, l0); split2(a.z, a.w, h1, l1);
    split2(b.x, b.y, h2, l2); split2(b.z, b.w, h3, l3);
    *(uint4*)(hi + o) = make_uint4(h0, h1, h2, h3);
    *(uint4*)(lo + o) = make_uint4(l0, l1, l2, l3);
}

// ---------------------------------------------------------------------------
// bf16x3 GEMM, pre-split operands, cp.async double-buffered.
// C[M,512] = A[M,512] @ W[512,512]; tile 128x128, BK=32, 8 warps (64x32 each).
// grid.z selects weight plane (z*C*C) and split-out plane (z*NTOK*C).
// Output: fp32 (Cf, +bias) or split bf16 (Chi/Clo).
// ---------------------------------------------------------------------------
#define GSA 40
#define GSB 136
#define APL 10240              // 128*40*2
#define BPL 8704               // 32*136*2
#define STG 37888              // 2*APL + 2*BPL
#define GEMM_SMEM (2 * STG)    // 75776

__global__ __launch_bounds__(256) void gemm_tc(
    const uint16_t* __restrict__ Ahi, const uint16_t* __restrict__ Alo,
    const uint16_t* __restrict__ Whi, const uint16_t* __restrict__ Wlo,
    float* __restrict__ Cf, const float* __restrict__ bias,
    uint16_t* __restrict__ Chi, uint16_t* __restrict__ Clo)
{
    extern __shared__ char sm[];
    const uint32_t smb = smem_u32(sm);
    const int tid = threadIdx.x;
    const int wid = tid >> 5, lane = tid & 31;
    const int g = lane >> 2, tig = lane & 3;
    const int wm = wid >> 2, wn = wid & 3;
    const int n0 = blockIdx.x * 128, m0 = blockIdx.y * 128;
    const uint16_t* Wh = Whi + (size_t)blockIdx.z * CC;
    const uint16_t* Wl = Wlo + (size_t)blockIdx.z * CC;
    const size_t zO = (size_t)blockIdx.z * NC;

    float c[4][4][4];
#pragma unroll
    for (int i = 0; i < 4; i++)
#pragma unroll
        for (int j = 0; j < 4; j++)
#pragma unroll
            for (int e = 0; e < 4; e++) c[i][j][e] = 0.f;

    auto preload = [&](int chunk, int buf) {
        const uint32_t sb = smb + buf * STG;
        const int k0 = chunk * 32;
#pragma unroll
        for (int rep = 0; rep < 2; rep++) {
            const int cc = tid + rep * 256;
            {   // A planes: 512 chunks each (128 rows x 4)
                const int row = cc >> 2, kc = cc & 3;
                const uint32_t d = sb + row * 80 + kc * 16;
                const size_t so = (size_t)(m0 + row) * C_ + k0 + kc * 8;
                cpa16(d, Ahi + so);
                cpa16(d + APL, Alo + so);
            }
            {   // B planes: 512 chunks each (32 rows x 16)
                const int row = cc >> 4, nc = cc & 15;
                const uint32_t d = sb + 2 * APL + row * 272 + nc * 16;
                const size_t so = (size_t)(k0 + row) * C_ + n0 + nc * 8;
                cpa16(d, Wh + so);
                cpa16(d + BPL, Wl + so);
            }
        }
    };

    auto compute = [&](int buf) {
        const uint32_t sb = smb + buf * STG;
#pragma unroll
        for (int kk = 0; kk < 32; kk += 16) {
            uint32_t ah[4][4], al[4][4];
#pragma unroll
            for (int mf = 0; mf < 4; mf++) {
                const uint32_t ae =
                    (uint32_t)((wm * 64 + mf * 16 + (lane & 15)) * GSA +
                               kk + ((lane >> 4) << 3)) * 2;
                ldsm4(ah[mf], sb + ae);
                ldsm4(al[mf], sb + APL + ae);
            }
            uint32_t bh[4][2], bl[4][2];
#pragma unroll
            for (int nfp = 0; nfp < 2; nfp++) {
                const uint32_t be =
                    (uint32_t)((kk + (lane & 7) + (((lane >> 3) & 1) << 3)) * GSB +
                               wn * 32 + nfp * 16 + ((lane >> 4) << 3)) * 2;
                uint32_t r[4];
                ldsm4t(r, sb + 2 * APL + be);
                bh[nfp * 2][0] = r[0]; bh[nfp * 2][1] = r[1];
                bh[nfp * 2 + 1][0] = r[2]; bh[nfp * 2 + 1][1] = r[3];
                ldsm4t(r, sb + 2 * APL + BPL + be);
                bl[nfp * 2][0] = r[0]; bl[nfp * 2][1] = r[1];
                bl[nfp * 2 + 1][0] = r[2]; bl[nfp * 2 + 1][1] = r[3];
            }
#pragma unroll
            for (int mf = 0; mf < 4; mf++)
#pragma unroll
                for (int nf = 0; nf < 4; nf++) {
                    mma16816(c[mf][nf], ah[mf], bh[nf]);
                    mma16816(c[mf][nf], ah[mf], bl[nf]);
                    mma16816(c[mf][nf], al[mf], bh[nf]);
                }
        }
    };

    preload(0, 0);
    CPA_COMMIT();
    for (int ch = 0; ch < 16; ch++) {
        if (ch < 15) {
            preload(ch + 1, (ch + 1) & 1);
            CPA_COMMIT();
            CPA_WAIT1();
        } else {
            CPA_WAIT0();
        }
        __syncthreads();
        compute(ch & 1);
        __syncthreads();
    }

    // Epilogue
#pragma unroll
    for (int mf = 0; mf < 4; mf++) {
        const int row0 = m0 + wm * 64 + mf * 16 + g;
        const int row1 = row0 + 8;
#pragma unroll
        for (int nf = 0; nf < 4; nf++) {
            const int col = n0 + wn * 32 + nf * 8 + tig * 2;
            if (Cf) {
                float bx = 0.f, by = 0.f;
                if (bias) { bx = bias[col]; by = bias[col + 1]; }
                *(float2*)(Cf + (size_t)row0 * C_ + col) =
                    make_float2(c[mf][nf][0] + bx, c[mf][nf][1] + by);
                *(float2*)(Cf + (size_t)row1 * C_ + col) =
                    make_float2(c[mf][nf][2] + bx, c[mf][nf][3] + by);
            } else {
                uint32_t hi, lo;
                split2(c[mf][nf][0], c[mf][nf][1], hi, lo);
                *(uint32_t*)(Chi + zO + (size_t)row0 * C_ + col) = hi;
                *(uint32_t*)(Clo + zO + (size_t)row0 * C_ + col) = lo;
                split2(c[mf][nf][2], c[mf][nf][3], hi, lo);
                *(uint32_t*)(Chi + zO + (size_t)row1 * C_ + col) = hi;
                *(uint32_t*)(Clo + zO + (size_t)row1 * C_ + col) = lo;
            }
        }
    }
}

// ---------------------------------------------------------------------------
// LayerNorm over 512; optional residual; output fp32 and/or split bf16.
// ---------------------------------------------------------------------------
__global__ __launch_bounds__(128) void ln_k(
    const float* __restrict__ in, const float* __restrict__ res,
    const float* __restrict__ w, const float* __restrict__ b,
    float* __restrict__ out, uint16_t* __restrict__ ohi,
    uint16_t* __restrict__ olo)
{
    const int row = blockIdx.x;
    const int t = threadIdx.x;

    float4 v = *(const float4*)(in + (size_t)row * C_ + t * 4);
    if (res) {
        float4 r = *(const float4*)(res + (size_t)row * C_ + t * 4);
        v.x += r.x; v.y += r.y; v.z += r.z; v.w += r.w;
    }
    float s  = v.x + v.y + v.z + v.w;
    float s2 = v.x * v.x + v.y * v.y + v.z * v.z + v.w * v.w;
#pragma unroll
    for (int o = 16; o; o >>= 1) {
        s  += __shfl_xor_sync(0xffffffffu, s,  o);
        s2 += __shfl_xor_sync(0xffffffffu, s2, o);
    }
    __shared__ float rs[4], rs2[4];
    const int wid = t >> 5;
    if ((t & 31) == 0) { rs[wid] = s; rs2[wid] = s2; }
    __syncthreads();
    float S  = rs[0]  + rs[1]  + rs[2]  + rs[3];
    float S2 = rs2[0] + rs2[1] + rs2[2] + rs2[3];
    const float mean = S * (1.f / C_);
    const float var  = S2 * (1.f / C_) - mean * mean;
    const float inv  = rsqrtf(var + LN_EPS);

    float4 wv = *(const float4*)(w + t * 4);
    float4 bv = *(const float4*)(b + t * 4);
    float4 o;
    o.x = (v.x - mean) * inv * wv.x + bv.x;
    o.y = (v.y - mean) * inv * wv.y + bv.y;
    o.z = (v.z - mean) * inv * wv.z + bv.z;
    o.w = (v.w - mean) * inv * wv.w + bv.w;
    if (out)
        *(float4*)(out + (size_t)row * C_ + t * 4) = o;
    if (ohi) {
        uint32_t h0, l0, h1, l1;
        split2(o.x, o.y, h0, l0);
        split2(o.z, o.w, h1, l1);
        *(uint2*)(ohi + (size_t)row * C_ + t * 4) = make_uint2(h0, h1);
        *(uint2*)(olo + (size_t)row * C_ + t * 4) = make_uint2(l0, l1);
    }
}

// ---------------------------------------------------------------------------
// Flash attention, bf16x3 mma.sync, causal. Pre-split Q/K/V inputs,
// split output. 64 q-rows per block, 256 threads = 8 warps.
// ---------------------------------------------------------------------------
#define FS 72
#define FOFF_QHI 0
#define FOFF_QLO 9216
#define FOFF_KHI 18432
#define FOFF_KLO 27648
#define FOFF_VHI 36864
#define FOFF_VLO 46080
#define FOFF_PHI 55296
#define FOFF_PLO 64512
#define FOFF_ST  73728
#define FLASH_SMEM 75264

__global__ __launch_bounds__(256) void flash_k(
    const uint16_t* __restrict__ QKVhi, const uint16_t* __restrict__ QKVlo,
    uint16_t* __restrict__ Ohi, uint16_t* __restrict__ Olo)
{
    extern __shared__ char sm[];
    const uint32_t smb = smem_u32(sm);
    float* stf = (float*)(sm + FOFF_ST);

    const int tid = threadIdx.x;
    const int wid = tid >> 5, lane = tid & 31;
    const int g = lane >> 2, tig = lane & 3;
    const int mw = wid >> 1, nw = wid & 1;

    const int qt = blockIdx.x;
    const int bh = blockIdx.y;
    const int b  = bh >> 3, h = bh & 7;
    const size_t base = (size_t)b * S_ * C_ + (size_t)h * D_;
    const int q0 = qt * 64;

    const uint16_t* Qhi = QKVhi + base;
    const uint16_t* Qlo = QKVlo + base;
    const uint16_t* Khi = QKVhi + NC + base;
    const uint16_t* Klo = QKVlo + NC + base;
    const uint16_t* Vhi = QKVhi + 2 * NC + base;
    const uint16_t* Vlo = QKVlo + 2 * NC + base;

    // Copy Q tile (64x64 bf16, hi+lo)
    for (int i = tid; i < 512; i += 256) {
        const int row = i >> 3, ch = i & 7;
        const size_t so = (size_t)(q0 + row) * C_ + ch * 8;
        const uint32_t d = (uint32_t)(row * FS + ch * 8) * 2;
        *(uint4*)(sm + FOFF_QHI + d) = *(const uint4*)(Qhi + so);
        *(uint4*)(sm + FOFF_QLO + d) = *(const uint4*)(Qlo + so);
    }
    if (tid < 64) { stf[tid] = -1e30f; stf[64 + tid] = 0.f; }

    float acc[4][4];
#pragma unroll
    for (int i = 0; i < 4; i++)
#pragma unroll
        for (int j = 0; j < 4; j++) acc[i][j] = 0.f;

    const int rl0 = mw * 16 + g, rl1 = rl0 + 8;

    for (int kt = 0; kt <= qt; kt++) {
        __syncthreads();
        const int k0g = kt * 64;
        for (int i = tid; i < 512; i += 256) {
            const int row = i >> 3, ch = i & 7;
            const size_t so = (size_t)(k0g + row) * C_ + ch * 8;
            const uint32_t d = (uint32_t)(row * FS + ch * 8) * 2;
            *(uint4*)(sm + FOFF_KHI + d) = *(const uint4*)(Khi + so);
            *(uint4*)(sm + FOFF_KLO + d) = *(const uint4*)(Klo + so);
            *(uint4*)(sm + FOFF_VHI + d) = *(const uint4*)(Vhi + so);
            *(uint4*)(sm + FOFF_VLO + d) = *(const uint4*)(Vlo + so);
        }
        __syncthreads();

        // ---- scores S = Q @ K^T ----
        float s[4][4];
#pragma unroll
        for (int i = 0; i < 4; i++)
#pragma unroll
            for (int j = 0; j < 4; j++) s[i][j] = 0.f;

#pragma unroll
        for (int kf = 0; kf < 4; kf++) {
            const uint32_t ae =
                (uint32_t)((mw * 16 + (lane & 15)) * FS + kf * 16 +
                           ((lane >> 4) << 3)) * 2;
            uint32_t aqh[4], aql[4];
            ldsm4(aqh, smb + FOFF_QHI + ae);
            ldsm4(aql, smb + FOFF_QLO + ae);
            uint32_t bkh[4][2], bkl[4][2];
#pragma unroll
            for (int nfp = 0; nfp < 2; nfp++) {
                const uint32_t be =
                    (uint32_t)((nw * 32 + nfp * 16 + (lane & 7) +
                                ((lane >> 4) << 3)) * FS +
                               kf * 16 + (((lane >> 3) & 1) << 3)) * 2;
                uint32_t r[4];
                ldsm4(r, smb + FOFF_KHI + be);
                bkh[nfp * 2][0] = r[0]; bkh[nfp * 2][1] = r[1];
                bkh[nfp * 2 + 1][0] = r[2]; bkh[nfp * 2 + 1][1] = r[3];
                ldsm4(r, smb + FOFF_KLO + be);
                bkl[nfp * 2][0] = r[0]; bkl[nfp * 2][1] = r[1];
                bkl[nfp * 2 + 1][0] = r[2]; bkl[nfp * 2 + 1][1] = r[3];
            }
#pragma unroll
            for (int nf = 0; nf < 4; nf++) {
                mma16816(s[nf], aqh, bkh[nf]);
                mma16816(s[nf], aqh, bkl[nf]);
                mma16816(s[nf], aql, bkh[nf]);
            }
        }

        const bool diag = (kt == qt);
#pragma unroll
        for (int nf = 0; nf < 4; nf++) {
#pragma unroll
            for (int e = 0; e < 4; e++) s[nf][e] *= ATT_SCALE;
            if (diag) {
                const int cc = nw * 32 + nf * 8 + tig * 2;
                if (cc     > rl0) s[nf][0] = -1e30f;
                if (cc + 1 > rl0) s[nf][1] = -1e30f;
                if (cc     > rl1) s[nf][2] = -1e30f;
                if (cc + 1 > rl1) s[nf][3] = -1e30f;
            }
        }

        float r0m = -1e30f, r1m = -1e30f;
#pragma unroll
        for (int nf = 0; nf < 4; nf++) {
            r0m = fmaxf(r0m, fmaxf(s[nf][0], s[nf][1]));
            r1m = fmaxf(r1m, fmaxf(s[nf][2], s[nf][3]));
        }
        r0m = fmaxf(r0m, __shfl_xor_sync(0xffffffffu, r0m, 1));
        r0m = fmaxf(r0m, __shfl_xor_sync(0xffffffffu, r0m, 2));
        r1m = fmaxf(r1m, __shfl_xor_sync(0xffffffffu, r1m, 1));
        r1m = fmaxf(r1m, __shfl_xor_sync(0xffffffffu, r1m, 2));
        if (tig == 0) {
            stf[256 + nw * 64 + rl0] = r0m;
            stf[256 + nw * 64 + rl1] = r1m;
        }
        __syncthreads();
        if (tid < 64) {
            const float mo = stf[tid];
            const float mx = fmaxf(stf[256 + tid], stf[320 + tid]);
            const float mn = fmaxf(mo, mx);
            stf[192 + tid] = mn;
            stf[128 + tid] = __expf(mo - mn);
            stf[tid] = mn;
        }
        __syncthreads();

        const float mn0 = stf[192 + rl0], mn1 = stf[192 + rl1];
        const float cr0 = stf[128 + rl0], cr1 = stf[128 + rl1];
        float rs0 = 0.f, rs1 = 0.f;
#pragma unroll
        for (int nf = 0; nf < 4; nf++) {
            acc[nf][0] *= cr0; acc[nf][1] *= cr0;
            acc[nf][2] *= cr1; acc[nf][3] *= cr1;
            const float p00 = __expf(s[nf][0] - mn0);
            const float p01 = __expf(s[nf][1] - mn0);
            const float p10 = __expf(s[nf][2] - mn1);
            const float p11 = __expf(s[nf][3] - mn1);
            rs0 += p00 + p01; rs1 += p10 + p11;
            const int cb = nw * 32 + nf * 8 + tig * 2;
            uint32_t hi, lo;
            split2(p00, p01, hi, lo);
            *(uint32_t*)(sm + FOFF_PHI + (uint32_t)(rl0 * FS + cb) * 2) = hi;
            *(uint32_t*)(sm + FOFF_PLO + (uint32_t)(rl0 * FS + cb) * 2) = lo;
            split2(p10, p11, hi, lo);
            *(uint32_t*)(sm + FOFF_PHI + (uint32_t)(rl1 * FS + cb) * 2) = hi;
            *(uint32_t*)(sm + FOFF_PLO + (uint32_t)(rl1 * FS + cb) * 2) = lo;
        }
        rs0 += __shfl_xor_sync(0xffffffffu, rs0, 1);
        rs0 += __shfl_xor_sync(0xffffffffu, rs0, 2);
        rs1 += __shfl_xor_sync(0xffffffffu, rs1, 1);
        rs1 += __shfl_xor_sync(0xffffffffu, rs1, 2);
        if (tig == 0) {
            stf[256 + nw * 64 + rl0] = rs0;
            stf[256 + nw * 64 + rl1] = rs1;
        }
        __syncthreads();
        if (tid < 64) {
            stf[64 + tid] = stf[64 + tid] * stf[128 + tid] +
                            stf[256 + tid] + stf[320 + tid];
        }

        // ---- PV ----
#pragma unroll
        for (int kf = 0; kf < 4; kf++) {
            const uint32_t ae =
                (uint32_t)((mw * 16 + (lane & 15)) * FS + kf * 16 +
                           ((lane >> 4) << 3)) * 2;
            uint32_t aph[4], apl[4];
            ldsm4(aph, smb + FOFF_PHI + ae);
            ldsm4(apl, smb + FOFF_PLO + ae);
            uint32_t bvh[4][2], bvl[4][2];
#pragma unroll
            for (int nfp = 0; nfp < 2; nfp++) {
                const uint32_t be =
                    (uint32_t)((kf * 16 + (lane & 7) + (((lane >> 3) & 1) << 3)) * FS +
                               nw * 32 + nfp * 16 + ((lane >> 4) << 3)) * 2;
                uint32_t r[4];
                ldsm4t(r, smb + FOFF_VHI + be);
                bvh[nfp * 2][0] = r[0]; bvh[nfp * 2][1] = r[1];
                bvh[nfp * 2 + 1][0] = r[2]; bvh[nfp * 2 + 1][1] = r[3];
                ldsm4t(r, smb + FOFF_VLO + be);
                bvl[nfp * 2][0] = r[0]; bvl[nfp * 2][1] = r[1];
                bvl[nfp * 2 + 1][0] = r[2]; bvl[nfp * 2 + 1][1] = r[3];
            }
#pragma unroll
            for (int nf = 0; nf < 4; nf++) {
                mma16816(acc[nf], aph, bvh[nf]);
                mma16816(acc[nf], aph, bvl[nf]);
                mma16816(acc[nf], apl, bvh[nf]);
            }
        }
    }
    __syncthreads();

    const float il0 = 1.f / stf[64 + rl0];
    const float il1 = 1.f / stf[64 + rl1];
#pragma unroll
    for (int nf = 0; nf < 4; nf++) {
        const int col = nw * 32 + nf * 8 + tig * 2;
        uint32_t hi, lo;
        split2(acc[nf][0] * il0, acc[nf][1] * il0, hi, lo);
        *(uint32_t*)(Ohi + base + (size_t)(q0 + rl0) * C_ + col) = hi;
        *(uint32_t*)(Olo + base + (size_t)(q0 + rl0) * C_ + col) = lo;
        split2(acc[nf][2] * il1, acc[nf][3] * il1, hi, lo);
        *(uint32_t*)(Ohi + base + (size_t)(q0 + rl1) * C_ + col) = hi;
        *(uint32_t*)(Olo + base + (size_t)(q0 + rl1) * C_ + col) = lo;
    }
}

// ---------------------------------------------------------------------------
// Launcher
// ---------------------------------------------------------------------------
extern "C" void kernel_launch(void* const* d_in, const int* in_sizes, int n_in,
                              void* d_out, int out_size)
{
    (void)in_sizes; (void)n_in; (void)out_size;

    const float* x        = (const float*)d_in[0];
    const float* Wq       = (const float*)d_in[1];
    const float* Wk       = (const float*)d_in[2];
    const float* Wv       = (const float*)d_in[3];
    const float* Wo       = (const float*)d_in[4];
    const float* ln1_w    = (const float*)d_in[5];
    const float* ln1_b    = (const float*)d_in[6];
    const float* ff_ln1_w = (const float*)d_in[7];
    const float* ff_ln1_b = (const float*)d_in[8];
    const float* ff_w1    = (const float*)d_in[9];
    const float* ff_b1    = (const float*)d_in[10];
    const float* ff_ln2_w = (const float*)d_in[11];
    const float* ff_ln2_b = (const float*)d_in[12];
    const float* ff_w2    = (const float*)d_in[13];
    const float* ff_b2    = (const float*)d_in[14];
    const float* ln2_w    = (const float*)d_in[15];
    const float* ln2_b    = (const float*)d_in[16];
    float* out = (float*)d_out;

    float *t0, *xln, *t1;
    uint16_t *xhi, *xlo, *whi, *wlo, *qkvhi, *qkvlo, *atthi, *attlo, *t0hi, *t0lo;
    cudaGetSymbolAddress((void**)&t0,    g_t0);
    cudaGetSymbolAddress((void**)&xln,   g_xln);
    cudaGetSymbolAddress((void**)&t1,    g_t1);
    cudaGetSymbolAddress((void**)&xhi,   g_xhi);
    cudaGetSymbolAddress((void**)&xlo,   g_xlo);
    cudaGetSymbolAddress((void**)&whi,   g_whi);
    cudaGetSymbolAddress((void**)&wlo,   g_wlo);
    cudaGetSymbolAddress((void**)&qkvhi, g_qkvhi);
    cudaGetSymbolAddress((void**)&qkvlo, g_qkvlo);
    cudaGetSymbolAddress((void**)&atthi, g_atthi);
    cudaGetSymbolAddress((void**)&attlo, g_attlo);
    cudaGetSymbolAddress((void**)&t0hi,  g_t0hi);
    cudaGetSymbolAddress((void**)&t0lo,  g_t0lo);

    cudaFuncSetAttribute(flash_k, cudaFuncAttributeMaxDynamicSharedMemorySize,
                         FLASH_SMEM);
    cudaFuncSetAttribute(gemm_tc, cudaFuncAttributeMaxDynamicSharedMemorySize,
                         GEMM_SMEM);

    // Split inputs
    split1_k<<<(int)(NC / 2048), 256>>>(x, xhi, xlo);
    splitw_k<<<dim3((int)(CC / 2048), 1, 6), 256>>>(Wq, Wk, Wv, Wo, ff_w1, ff_w2,
                                                    whi, wlo);

    const dim3 g3(C_ / 128, NTOK / 128, 3);
    const dim3 g1(C_ / 128, NTOK / 128, 1);

    // QKV projections -> split q/k/v
    gemm_tc<<<g3, 256, GEMM_SMEM>>>(xhi, xlo, whi, wlo,
                                    nullptr, nullptr, qkvhi, qkvlo);

    // Causal flash attention -> split att
    flash_k<<<dim3(S_ / 64, B_ * H_), 256, FLASH_SMEM>>>(qkvhi, qkvlo,
                                                         atthi, attlo);

    // Output projection (weight plane 3) -> fp32 t0
    gemm_tc<<<g1, 256, GEMM_SMEM>>>(atthi, attlo, whi + 3 * CC, wlo + 3 * CC,
                                    t0, nullptr, nullptr, nullptr);

    // x_ln = LN(attn_out + x)   (fp32)
    ln_k<<<NTOK, 128>>>(t0, x, ln1_w, ln1_b, xln, nullptr, nullptr);

    // h = LN(x_ln) @ ff_w1 + b1
    ln_k<<<NTOK, 128>>>(xln, nullptr, ff_ln1_w, ff_ln1_b, nullptr, t0hi, t0lo);
    gemm_tc<<<g1, 256, GEMM_SMEM>>>(t0hi, t0lo, whi + 4 * CC, wlo + 4 * CC,
                                    t1, ff_b1, nullptr, nullptr);

    // h = LN(h) @ ff_w2 + b2
    ln_k<<<NTOK, 128>>>(t1, nullptr, ff_ln2_w, ff_ln2_b, nullptr, t0hi, t0lo);
    gemm_tc<<<g1, 256, GEMM_SMEM>>>(t0hi, t0lo, whi + 5 * CC, wlo + 5 * CC,
                                    t1, ff_b2, nullptr, nullptr);

    // out = LN(h + x_ln)
    ln_k<<<NTOK, 128>>>(t1, xln, ln2_w, ln2_b, out, nullptr, nullptr);
}

// round 5
// speedup vs baseline: 3.0635x; 1.0708x over previous
#include <cuda_runtime.h>
#include <cuda_bf16.h>
#include <math.h>
#include <stdint.h>

#define B_ 4
#define S_ 2048
#define C_ 512
#define H_ 8
#define D_ 64
#define NTOK (B_ * S_)
#define ATT_SCALE 0.125f
#define LN_EPS 1e-5f
#define NC ((size_t)NTOK * C_)
#define CC ((size_t)C_ * C_)

// ---------------------------------------------------------------------------
// Scratch buffers
// ---------------------------------------------------------------------------
__device__ float g_t0 [NC];
__device__ float g_xln[NC];
__device__ float g_t1 [NC];

__device__ uint16_t g_xhi [NC],     g_xlo [NC];
__device__ uint16_t g_whi [6 * CC], g_wlo [6 * CC];
__device__ uint16_t g_qkvhi[3 * NC], g_qkvlo[3 * NC];
__device__ uint16_t g_atthi[NC],    g_attlo[NC];
__device__ uint16_t g_t0hi[NC],     g_t0lo[NC];

// ---------------------------------------------------------------------------
// Helpers
// ---------------------------------------------------------------------------
__device__ __forceinline__ uint32_t smem_u32(const void* p) {
    uint32_t a;
    asm("{ .reg .u64 t; cvta.to.shared.u64 t, %1; cvt.u32.u64 %0, t; }"
        : "=r"(a) : "l"(p));
    return a;
}
__device__ __forceinline__ void ldsm4(uint32_t* r, uint32_t addr) {
    asm volatile("ldmatrix.sync.aligned.m8n8.x4.shared.b16 {%0,%1,%2,%3}, [%4];"
                 : "=r"(r[0]), "=r"(r[1]), "=r"(r[2]), "=r"(r[3]) : "r"(addr));
}
__device__ __forceinline__ void ldsm4t(uint32_t* r, uint32_t addr) {
    asm volatile("ldmatrix.sync.aligned.m8n8.x4.trans.shared.b16 {%0,%1,%2,%3}, [%4];"
                 : "=r"(r[0]), "=r"(r[1]), "=r"(r[2]), "=r"(r[3]) : "r"(addr));
}
__device__ __forceinline__ void mma16816(float* c, const uint32_t* a, const uint32_t* b) {
    asm volatile(
        "mma.sync.aligned.m16n8k16.row.col.f32.bf16.bf16.f32 "
        "{%0,%1,%2,%3},{%4,%5,%6,%7},{%8,%9},{%0,%1,%2,%3};"
        : "+f"(c[0]), "+f"(c[1]), "+f"(c[2]), "+f"(c[3])
        : "r"(a[0]), "r"(a[1]), "r"(a[2]), "r"(a[3]), "r"(b[0]), "r"(b[1]));
}
__device__ __forceinline__ void cpa16(uint32_t dst, const void* src) {
    asm volatile("cp.async.cg.shared.global [%0], [%1], 16;" :: "r"(dst), "l"(src));
}
#define CPA_COMMIT() asm volatile("cp.async.commit_group;")
#define CPA_WAIT0()  asm volatile("cp.async.wait_group 0;")
#define CPA_WAIT1()  asm volatile("cp.async.wait_group 1;")

__device__ __forceinline__ uint16_t f2bf(float x) {
    __nv_bfloat16 b = __float2bfloat16(x);
    return *(uint16_t*)&b;
}
__device__ __forceinline__ float bf2f(uint16_t u) {
    __nv_bfloat16 b = *(__nv_bfloat16*)&u;
    return __bfloat162float(b);
}
__device__ __forceinline__ void split2(float x0, float x1, uint32_t& hi, uint32_t& lo) {
    uint16_t h0 = f2bf(x0), h1 = f2bf(x1);
    uint16_t l0 = f2bf(x0 - bf2f(h0)), l1 = f2bf(x1 - bf2f(h1));
    hi = (uint32_t)h0 | ((uint32_t)h1 << 16);
    lo = (uint32_t)l0 | ((uint32_t)l1 << 16);
}

// ---------------------------------------------------------------------------
// Split kernels
// ---------------------------------------------------------------------------
__global__ __launch_bounds__(256) void split1_k(
    const float* __restrict__ in, uint16_t* __restrict__ hi,
    uint16_t* __restrict__ lo)
{
    const size_t i = ((size_t)blockIdx.x * 256 + threadIdx.x) * 8;
    float4 a = *(const float4*)(in + i);
    float4 b = *(const float4*)(in + i + 4);
    uint32_t h0, l0, h1, l1, h2, l2, h3, l3;
    split2(a.x, a.y, h0, l0); split2(a.z, a.w, h1, l1);
    split2(b.x, b.y, h2, l2); split2(b.z, b.w, h3, l3);
    *(uint4*)(hi + i) = make_uint4(h0, h1, h2, h3);
    *(uint4*)(lo + i) = make_uint4(l0, l1, l2, l3);
}

__global__ __launch_bounds__(256) void splitw_k(
    const float* __restrict__ w0, const float* __restrict__ w1,
    const float* __restrict__ w2, const float* __restrict__ w3,
    const float* __restrict__ w4, const float* __restrict__ w5,
    uint16_t* __restrict__ hi, uint16_t* __restrict__ lo)
{
    const int z = blockIdx.z;
    const float* w = (z == 0) ? w0 : (z == 1) ? w1 : (z == 2) ? w2 :
                     (z == 3) ? w3 : (z == 4) ? w4 : w5;
    const size_t j = ((size_t)blockIdx.x * 256 + threadIdx.x) * 8;
    const size_t o = (size_t)z * CC + j;
    float4 a = *(const float4*)(w + j);
    float4 b = *(const float4*)(w + j + 4);
    uint32_t h0, l0, h1, l1, h2, l2, h3, l3;
    split2(a.x, a.y, h0, l0); split2(a.z, a.w, h1, l1);
    split2(b.x, b.y, h2, l2); split2(b.z, b.w, h3, l3);
    *(uint4*)(hi + o) = make_uint4(h0, h1, h2, h3);
    *(uint4*)(lo + o) = make_uint4(l0, l1, l2, l3);
}

// ---------------------------------------------------------------------------
// bf16x3 GEMM (unchanged from R4)
// ---------------------------------------------------------------------------
#define GSA 40
#define GSB 136
#define APL 10240
#define BPL 8704
#define STG 37888
#define GEMM_SMEM (2 * STG)

__global__ __launch_bounds__(256) void gemm_tc(
    const uint16_t* __restrict__ Ahi, const uint16_t* __restrict__ Alo,
    const uint16_t* __restrict__ Whi, const uint16_t* __restrict__ Wlo,
    float* __restrict__ Cf, const float* __restrict__ bias,
    uint16_t* __restrict__ Chi, uint16_t* __restrict__ Clo)
{
    extern __shared__ char sm[];
    const uint32_t smb = smem_u32(sm);
    const int tid = threadIdx.x;
    const int wid = tid >> 5, lane = tid & 31;
    const int g = lane >> 2, tig = lane & 3;
    const int wm = wid >> 2, wn = wid & 3;
    const int n0 = blockIdx.x * 128, m0 = blockIdx.y * 128;
    const uint16_t* Wh = Whi + (size_t)blockIdx.z * CC;
    const uint16_t* Wl = Wlo + (size_t)blockIdx.z * CC;
    const size_t zO = (size_t)blockIdx.z * NC;

    float c[4][4][4];
#pragma unroll
    for (int i = 0; i < 4; i++)
#pragma unroll
        for (int j = 0; j < 4; j++)
#pragma unroll
            for (int e = 0; e < 4; e++) c[i][j][e] = 0.f;

    auto preload = [&](int chunk, int buf) {
        const uint32_t sb = smb + buf * STG;
        const int k0 = chunk * 32;
#pragma unroll
        for (int rep = 0; rep < 2; rep++) {
            const int cc = tid + rep * 256;
            {
                const int row = cc >> 2, kc = cc & 3;
                const uint32_t d = sb + row * 80 + kc * 16;
                const size_t so = (size_t)(m0 + row) * C_ + k0 + kc * 8;
                cpa16(d, Ahi + so);
                cpa16(d + APL, Alo + so);
            }
            {
                const int row = cc >> 4, nc = cc & 15;
                const uint32_t d = sb + 2 * APL + row * 272 + nc * 16;
                const size_t so = (size_t)(k0 + row) * C_ + n0 + nc * 8;
                cpa16(d, Wh + so);
                cpa16(d + BPL, Wl + so);
            }
        }
    };

    auto compute = [&](int buf) {
        const uint32_t sb = smb + buf * STG;
#pragma unroll
        for (int kk = 0; kk < 32; kk += 16) {
            uint32_t ah[4][4], al[4][4];
#pragma unroll
            for (int mf = 0; mf < 4; mf++) {
                const uint32_t ae =
                    (uint32_t)((wm * 64 + mf * 16 + (lane & 15)) * GSA +
                               kk + ((lane >> 4) << 3)) * 2;
                ldsm4(ah[mf], sb + ae);
                ldsm4(al[mf], sb + APL + ae);
            }
            uint32_t bh[4][2], bl[4][2];
#pragma unroll
            for (int nfp = 0; nfp < 2; nfp++) {
                const uint32_t be =
                    (uint32_t)((kk + (lane & 7) + (((lane >> 3) & 1) << 3)) * GSB +
                               wn * 32 + nfp * 16 + ((lane >> 4) << 3)) * 2;
                uint32_t r[4];
                ldsm4t(r, sb + 2 * APL + be);
                bh[nfp * 2][0] = r[0]; bh[nfp * 2][1] = r[1];
                bh[nfp * 2 + 1][0] = r[2]; bh[nfp * 2 + 1][1] = r[3];
                ldsm4t(r, sb + 2 * APL + BPL + be);
                bl[nfp * 2][0] = r[0]; bl[nfp * 2][1] = r[1];
                bl[nfp * 2 + 1][0] = r[2]; bl[nfp * 2 + 1][1] = r[3];
            }
#pragma unroll
            for (int mf = 0; mf < 4; mf++)
#pragma unroll
                for (int nf = 0; nf < 4; nf++) {
                    mma16816(c[mf][nf], ah[mf], bh[nf]);
                    mma16816(c[mf][nf], ah[mf], bl[nf]);
                    mma16816(c[mf][nf], al[mf], bh[nf]);
                }
        }
    };

    preload(0, 0);
    CPA_COMMIT();
    for (int ch = 0; ch < 16; ch++) {
        if (ch < 15) {
            preload(ch + 1, (ch + 1) & 1);
            CPA_COMMIT();
            CPA_WAIT1();
        } else {
            CPA_WAIT0();
        }
        __syncthreads();
        compute(ch & 1);
        __syncthreads();
    }

#pragma unroll
    for (int mf = 0; mf < 4; mf++) {
        const int row0 = m0 + wm * 64 + mf * 16 + g;
        const int row1 = row0 + 8;
#pragma unroll
        for (int nf = 0; nf < 4; nf++) {
            const int col = n0 + wn * 32 + nf * 8 + tig * 2;
            if (Cf) {
                float bx = 0.f, by = 0.f;
                if (bias) { bx = bias[col]; by = bias[col + 1]; }
                *(float2*)(Cf + (size_t)row0 * C_ + col) =
                    make_float2(c[mf][nf][0] + bx, c[mf][nf][1] + by);
                *(float2*)(Cf + (size_t)row1 * C_ + col) =
                    make_float2(c[mf][nf][2] + bx, c[mf][nf][3] + by);
            } else {
                uint32_t hi, lo;
                split2(c[mf][nf][0], c[mf][nf][1], hi, lo);
                *(uint32_t*)(Chi + zO + (size_t)row0 * C_ + col) = hi;
                *(uint32_t*)(Clo + zO + (size_t)row0 * C_ + col) = lo;
                split2(c[mf][nf][2], c[mf][nf][3], hi, lo);
                *(uint32_t*)(Chi + zO + (size_t)row1 * C_ + col) = hi;
                *(uint32_t*)(Clo + zO + (size_t)row1 * C_ + col) = lo;
            }
        }
    }
}

// ---------------------------------------------------------------------------
// LayerNorm (unchanged)
// ---------------------------------------------------------------------------
__global__ __launch_bounds__(128) void ln_k(
    const float* __restrict__ in, const float* __restrict__ res,
    const float* __restrict__ w, const float* __restrict__ b,
    float* __restrict__ out, uint16_t* __restrict__ ohi,
    uint16_t* __restrict__ olo)
{
    const int row = blockIdx.x;
    const int t = threadIdx.x;

    float4 v = *(const float4*)(in + (size_t)row * C_ + t * 4);
    if (res) {
        float4 r = *(const float4*)(res + (size_t)row * C_ + t * 4);
        v.x += r.x; v.y += r.y; v.z += r.z; v.w += r.w;
    }
    float s  = v.x + v.y + v.z + v.w;
    float s2 = v.x * v.x + v.y * v.y + v.z * v.z + v.w * v.w;
#pragma unroll
    for (int o = 16; o; o >>= 1) {
        s  += __shfl_xor_sync(0xffffffffu, s,  o);
        s2 += __shfl_xor_sync(0xffffffffu, s2, o);
    }
    __shared__ float rs[4], rs2[4];
    const int wid = t >> 5;
    if ((t & 31) == 0) { rs[wid] = s; rs2[wid] = s2; }
    __syncthreads();
    float S  = rs[0]  + rs[1]  + rs[2]  + rs[3];
    float S2 = rs2[0] + rs2[1] + rs2[2] + rs2[3];
    const float mean = S * (1.f / C_);
    const float var  = S2 * (1.f / C_) - mean * mean;
    const float inv  = rsqrtf(var + LN_EPS);

    float4 wv = *(const float4*)(w + t * 4);
    float4 bv = *(const float4*)(b + t * 4);
    float4 o;
    o.x = (v.x - mean) * inv * wv.x + bv.x;
    o.y = (v.y - mean) * inv * wv.y + bv.y;
    o.z = (v.z - mean) * inv * wv.z + bv.z;
    o.w = (v.w - mean) * inv * wv.w + bv.w;
    if (out)
        *(float4*)(out + (size_t)row * C_ + t * 4) = o;
    if (ohi) {
        uint32_t h0, l0, h1, l1;
        split2(o.x, o.y, h0, l0);
        split2(o.z, o.w, h1, l1);
        *(uint2*)(ohi + (size_t)row * C_ + t * 4) = make_uint2(h0, h1);
        *(uint2*)(olo + (size_t)row * C_ + t * 4) = make_uint2(l0, l1);
    }
}

// ---------------------------------------------------------------------------
// FA2-style flash attention. Q tile = 128 rows, warp owns 16 rows x 64 cols.
// Per-warp register softmax (quad shuffles), register-resident P (C->A frag),
// cp.async double-buffered K/V. bf16x3 numerics identical to R4.
// ---------------------------------------------------------------------------
#define FS 72
#define PLANE 9216            // 64 * FS * 2
#define BUFSZ (4 * PLANE)     // Khi,Klo,Vhi,Vlo
#define FLASH_SMEM (2 * BUFSZ)

__global__ __launch_bounds__(256, 1) void flash_k(
    const uint16_t* __restrict__ QKVhi, const uint16_t* __restrict__ QKVlo,
    uint16_t* __restrict__ Ohi, uint16_t* __restrict__ Olo)
{
    extern __shared__ char sm[];
    const uint32_t smb = smem_u32(sm);

    const int tid = threadIdx.x;
    const int wid = tid >> 5, lane = tid & 31;
    const int g = lane >> 2, tig = lane & 3;

    const int qt = (gridDim.x - 1) - blockIdx.x;   // heavy tiles first
    const int bh = blockIdx.y;
    const int b  = bh >> 3, h = bh & 7;
    const size_t base = (size_t)b * S_ * C_ + (size_t)h * D_;
    const int q0 = qt * 128;
    const int wr0 = wid * 16;

    const uint16_t* Qhi = QKVhi + base;
    const uint16_t* Qlo = QKVlo + base;
    const uint16_t* Khi = QKVhi + NC + base;
    const uint16_t* Klo = QKVlo + NC + base;
    const uint16_t* Vhi = QKVhi + 2 * NC + base;
    const uint16_t* Vlo = QKVlo + 2 * NC + base;

    // ---- stage Q (128 rows hi/lo) through buf0, ldmatrix to registers ----
#pragma unroll
    for (int p = 0; p < 8; p++) {
        const int id = p * 256 + tid;               // 0..2047
        const int half = id >> 10;                  // rows 0-63 / 64-127
        const int pl = (id >> 9) & 1;               // hi / lo
        const int rl = (id & 511) >> 3;
        const int ch = id & 7;
        const uint32_t dst = smb + half * 2 * PLANE + pl * PLANE +
                             (uint32_t)(rl * FS + ch * 8) * 2;
        const uint16_t* src = (pl ? Qlo : Qhi) +
                              (size_t)(q0 + half * 64 + rl) * C_ + ch * 8;
        cpa16(dst, src);
    }
    CPA_COMMIT();
    CPA_WAIT0();
    __syncthreads();

    uint32_t qh[4][4], ql[4][4];
    {
        const uint32_t areaH = smb + ((wid >= 4) ? 2 * PLANE : 0);
        const int lw = (wid & 3) * 16;
#pragma unroll
        for (int kf = 0; kf < 4; kf++) {
            const uint32_t ae =
                (uint32_t)((lw + (lane & 15)) * FS + kf * 16 +
                           ((lane >> 4) << 3)) * 2;
            ldsm4(qh[kf], areaH + ae);
            ldsm4(ql[kf], areaH + PLANE + ae);
        }
    }
    __syncthreads();

    float acc[8][4];
#pragma unroll
    for (int i = 0; i < 8; i++)
#pragma unroll
        for (int e = 0; e < 4; e++) acc[i][e] = 0.f;
    float m0 = -1e30f, m1 = -1e30f, l0 = 0.f, l1 = 0.f;

    const int r0 = q0 + wr0 + g;
    const int r1 = r0 + 8;
    const int nkt = 2 * qt + 2;

    auto preload = [&](int kt, int buf) {
        const int k0 = kt * 64;
        const uint32_t bb = smb + buf * BUFSZ;
#pragma unroll
        for (int p = 0; p < 8; p++) {
            const int id = p * 256 + tid;
            const int pl = id >> 9;                 // 0..3
            const int rl = (id & 511) >> 3;
            const int ch = id & 7;
            const uint32_t dst = bb + pl * PLANE +
                                 (uint32_t)(rl * FS + ch * 8) * 2;
            const uint16_t* src =
                ((pl == 0) ? Khi : (pl == 1) ? Klo : (pl == 2) ? Vhi : Vlo) +
                (size_t)(k0 + rl) * C_ + ch * 8;
            cpa16(dst, src);
        }
    };

    preload(0, 0);
    CPA_COMMIT();

    for (int kt = 0; kt < nkt; kt++) {
        const int k0g = kt * 64;
        CPA_WAIT0();
        __syncthreads();
        if (kt + 1 < nkt) {
            preload(kt + 1, (kt + 1) & 1);
            CPA_COMMIT();
        }

        if (k0g <= q0 + wr0 + 15) {   // warp not fully masked
            const uint32_t kb = smb + (kt & 1) * BUFSZ;

            // ---- scores S = Q @ K^T (bf16x3) ----
            float s[8][4];
#pragma unroll
            for (int i = 0; i < 8; i++)
#pragma unroll
                for (int e = 0; e < 4; e++) s[i][e] = 0.f;

#pragma unroll
            for (int kf = 0; kf < 4; kf++) {
#pragma unroll
                for (int nfq = 0; nfq < 4; nfq++) {
                    const uint32_t be =
                        (uint32_t)((nfq * 16 + (lane & 7) + ((lane >> 4) << 3)) * FS +
                                   kf * 16 + (((lane >> 3) & 1) << 3)) * 2;
                    uint32_t rh[4], rl_[4];
                    ldsm4(rh, kb + be);
                    ldsm4(rl_, kb + PLANE + be);
                    mma16816(s[2 * nfq], qh[kf], rh);
                    mma16816(s[2 * nfq], qh[kf], rl_);
                    mma16816(s[2 * nfq], ql[kf], rh);
                    mma16816(s[2 * nfq + 1], qh[kf], rh + 2);
                    mma16816(s[2 * nfq + 1], qh[kf], rl_ + 2);
                    mma16816(s[2 * nfq + 1], ql[kf], rh + 2);
                }
            }

            // scale + causal mask
            const bool needmask = (k0g + 63 > q0 + wr0);
#pragma unroll
            for (int nf = 0; nf < 8; nf++) {
#pragma unroll
                for (int e = 0; e < 4; e++) s[nf][e] *= ATT_SCALE;
                if (needmask) {
                    const int cc = k0g + nf * 8 + tig * 2;
                    if (cc     > r0) s[nf][0] = -1e30f;
                    if (cc + 1 > r0) s[nf][1] = -1e30f;
                    if (cc     > r1) s[nf][2] = -1e30f;
                    if (cc + 1 > r1) s[nf][3] = -1e30f;
                }
            }

            // per-row max (quad shuffle)
            float ml0 = -1e30f, ml1 = -1e30f;
#pragma unroll
            for (int nf = 0; nf < 8; nf++) {
                ml0 = fmaxf(ml0, fmaxf(s[nf][0], s[nf][1]));
                ml1 = fmaxf(ml1, fmaxf(s[nf][2], s[nf][3]));
            }
            ml0 = fmaxf(ml0, __shfl_xor_sync(0xffffffffu, ml0, 1));
            ml0 = fmaxf(ml0, __shfl_xor_sync(0xffffffffu, ml0, 2));
            ml1 = fmaxf(ml1, __shfl_xor_sync(0xffffffffu, ml1, 1));
            ml1 = fmaxf(ml1, __shfl_xor_sync(0xffffffffu, ml1, 2));

            const float mn0 = fmaxf(m0, ml0);
            const float mn1 = fmaxf(m1, ml1);
            const float cr0 = __expf(m0 - mn0);
            const float cr1 = __expf(m1 - mn1);
            m0 = mn0; m1 = mn1;

            // exponentiate in place, accumulate row sums, rescale acc
            float rs0 = 0.f, rs1 = 0.f;
#pragma unroll
            for (int nf = 0; nf < 8; nf++) {
                s[nf][0] = __expf(s[nf][0] - mn0);
                s[nf][1] = __expf(s[nf][1] - mn0);
                s[nf][2] = __expf(s[nf][2] - mn1);
                s[nf][3] = __expf(s[nf][3] - mn1);
                rs0 += s[nf][0] + s[nf][1];
                rs1 += s[nf][2] + s[nf][3];
                acc[nf][0] *= cr0; acc[nf][1] *= cr0;
                acc[nf][2] *= cr1; acc[nf][3] *= cr1;
            }
            rs0 += __shfl_xor_sync(0xffffffffu, rs0, 1);
            rs0 += __shfl_xor_sync(0xffffffffu, rs0, 2);
            rs1 += __shfl_xor_sync(0xffffffffu, rs1, 1);
            rs1 += __shfl_xor_sync(0xffffffffu, rs1, 2);
            l0 = l0 * cr0 + rs0;
            l1 = l1 * cr1 + rs1;

            // ---- PV: acc += P @ V, P packed from registers ----
#pragma unroll
            for (int kf = 0; kf < 4; kf++) {
                uint32_t aph[4], apl[4];
                split2(s[2 * kf][0],     s[2 * kf][1],     aph[0], apl[0]);
                split2(s[2 * kf][2],     s[2 * kf][3],     aph[1], apl[1]);
                split2(s[2 * kf + 1][0], s[2 * kf + 1][1], aph[2], apl[2]);
                split2(s[2 * kf + 1][2], s[2 * kf + 1][3], aph[3], apl[3]);
#pragma unroll
                for (int nfq = 0; nfq < 4; nfq++) {
                    const uint32_t be =
                        (uint32_t)((kf * 16 + (lane & 7) + (((lane >> 3) & 1) << 3)) * FS +
                                   nfq * 16 + ((lane >> 4) << 3)) * 2;
                    uint32_t vh[4], vl[4];
                    ldsm4t(vh, kb + 2 * PLANE + be);
                    ldsm4t(vl, kb + 3 * PLANE + be);
                    mma16816(acc[2 * nfq], aph, vh);
                    mma16816(acc[2 * nfq], aph, vl);
                    mma16816(acc[2 * nfq], apl, vh);
                    mma16816(acc[2 * nfq + 1], aph, vh + 2);
                    mma16816(acc[2 * nfq + 1], aph, vl + 2);
                    mma16816(acc[2 * nfq + 1], apl, vh + 2);
                }
            }
        }
    }

    // ---- epilogue: normalize, split, store ----
    const float il0 = 1.f / l0;
    const float il1 = 1.f / l1;
#pragma unroll
    for (int nf = 0; nf < 8; nf++) {
        const int col = nf * 8 + tig * 2;
        uint32_t hi, lo;
        split2(acc[nf][0] * il0, acc[nf][1] * il0, hi, lo);
        *(uint32_t*)(Ohi + base + (size_t)r0 * C_ + col) = hi;
        *(uint32_t*)(Olo + base + (size_t)r0 * C_ + col) = lo;
        split2(acc[nf][2] * il1, acc[nf][3] * il1, hi, lo);
        *(uint32_t*)(Ohi + base + (size_t)r1 * C_ + col) = hi;
        *(uint32_t*)(Olo + base + (size_t)r1 * C_ + col) = lo;
    }
}

// ---------------------------------------------------------------------------
// Launcher
// ---------------------------------------------------------------------------
extern "C" void kernel_launch(void* const* d_in, const int* in_sizes, int n_in,
                              void* d_out, int out_size)
{
    (void)in_sizes; (void)n_in; (void)out_size;

    const float* x        = (const float*)d_in[0];
    const float* Wq       = (const float*)d_in[1];
    const float* Wk       = (const float*)d_in[2];
    const float* Wv       = (const float*)d_in[3];
    const float* Wo       = (const float*)d_in[4];
    const float* ln1_w    = (const float*)d_in[5];
    const float* ln1_b    = (const float*)d_in[6];
    const float* ff_ln1_w = (const float*)d_in[7];
    const float* ff_ln1_b = (const float*)d_in[8];
    const float* ff_w1    = (const float*)d_in[9];
    const float* ff_b1    = (const float*)d_in[10];
    const float* ff_ln2_w = (const float*)d_in[11];
    const float* ff_ln2_b = (const float*)d_in[12];
    const float* ff_w2    = (const float*)d_in[13];
    const float* ff_b2    = (const float*)d_in[14];
    const float* ln2_w    = (const float*)d_in[15];
    const float* ln2_b    = (const float*)d_in[16];
    float* out = (float*)d_out;

    float *t0, *xln, *t1;
    uint16_t *xhi, *xlo, *whi, *wlo, *qkvhi, *qkvlo, *atthi, *attlo, *t0hi, *t0lo;
    cudaGetSymbolAddress((void**)&t0,    g_t0);
    cudaGetSymbolAddress((void**)&xln,   g_xln);
    cudaGetSymbolAddress((void**)&t1,    g_t1);
    cudaGetSymbolAddress((void**)&xhi,   g_xhi);
    cudaGetSymbolAddress((void**)&xlo,   g_xlo);
    cudaGetSymbolAddress((void**)&whi,   g_whi);
    cudaGetSymbolAddress((void**)&wlo,   g_wlo);
    cudaGetSymbolAddress((void**)&qkvhi, g_qkvhi);
    cudaGetSymbolAddress((void**)&qkvlo, g_qkvlo);
    cudaGetSymbolAddress((void**)&atthi, g_atthi);
    cudaGetSymbolAddress((void**)&attlo, g_attlo);
    cudaGetSymbolAddress((void**)&t0hi,  g_t0hi);
    cudaGetSymbolAddress((void**)&t0lo,  g_t0lo);

    cudaFuncSetAttribute(flash_k, cudaFuncAttributeMaxDynamicSharedMemorySize,
                         FLASH_SMEM);
    cudaFuncSetAttribute(gemm_tc, cudaFuncAttributeMaxDynamicSharedMemorySize,
                         GEMM_SMEM);

    // Split inputs
    split1_k<<<(int)(NC / 2048), 256>>>(x, xhi, xlo);
    splitw_k<<<dim3((int)(CC / 2048), 1, 6), 256>>>(Wq, Wk, Wv, Wo, ff_w1, ff_w2,
                                                    whi, wlo);

    const dim3 g3(C_ / 128, NTOK / 128, 3);
    const dim3 g1(C_ / 128, NTOK / 128, 1);

    // QKV projections -> split q/k/v
    gemm_tc<<<g3, 256, GEMM_SMEM>>>(xhi, xlo, whi, wlo,
                                    nullptr, nullptr, qkvhi, qkvlo);

    // Causal flash attention -> split att
    flash_k<<<dim3(S_ / 128, B_ * H_), 256, FLASH_SMEM>>>(qkvhi, qkvlo,
                                                          atthi, attlo);

    // Output projection -> fp32 t0
    gemm_tc<<<g1, 256, GEMM_SMEM>>>(atthi, attlo, whi + 3 * CC, wlo + 3 * CC,
                                    t0, nullptr, nullptr, nullptr);

    // x_ln = LN(attn_out + x)
    ln_k<<<NTOK, 128>>>(t0, x, ln1_w, ln1_b, xln, nullptr, nullptr);

    // h = LN(x_ln) @ ff_w1 + b1
    ln_k<<<NTOK, 128>>>(xln, nullptr, ff_ln1_w, ff_ln1_b, nullptr, t0hi, t0lo);
    gemm_tc<<<g1, 256, GEMM_SMEM>>>(t0hi, t0lo, whi + 4 * CC, wlo + 4 * CC,
                                    t1, ff_b1, nullptr, nullptr);

    // h = LN(h) @ ff_w2 + b2
    ln_k<<<NTOK, 128>>>(t1, nullptr, ff_ln2_w, ff_ln2_b, nullptr, t0hi, t0lo);
    gemm_tc<<<g1, 256, GEMM_SMEM>>>(t0hi, t0lo, whi + 5 * CC, wlo + 5 * CC,
                                    t1, ff_b2, nullptr, nullptr);

    // out = LN(h + x_ln)
    ln_k<<<NTOK, 128>>>(t1, xln, ln2_w, ln2_b, out, nullptr, nullptr);
}